// round 1
// baseline (speedup 1.0000x reference)
#include <cuda_runtime.h>
#include <math.h>

#define NB 2
#define NS 2048
#define ND 768
#define NH 12
#define NDK 64
#define NM (NB * NS)   // 4096 rows total

// Scratch (static device globals -- no runtime allocation allowed).
__device__ float g_q[(size_t)NB * NH * NS * NDK];   // [b][h][s][dk]
__device__ float g_k[(size_t)NB * NH * NS * NDK];
__device__ float g_v[(size_t)NB * NH * NS * NDK];
__device__ float g_ctx[(size_t)NB * NS * ND];       // [b][s][d]

// ---------------------------------------------------------------------------
// GEMM: out = X @ W^T.  X: (NM, ND) row-major, W: (ND, ND) row-major.
// MODE 0/1/2: X = input Q/K/V, write head-split into g_q/g_k/g_v.
// MODE 3:     X = g_ctx, write flat into outp (d_out).
// 64x64 block tile, 256 threads, 4x4 microtile, K-tile = 16.
// ---------------------------------------------------------------------------
template <int MODE>
__global__ __launch_bounds__(256) void gemm_xwt(const float* __restrict__ Xin,
                                                const float* __restrict__ W,
                                                float* __restrict__ outp) {
    __shared__ float As[64][17];
    __shared__ float Bs[64][17];
    const float* X = (MODE == 3) ? g_ctx : Xin;
    const int tid = threadIdx.x;
    const int tx = tid & 15, ty = tid >> 4;
    const int m0 = blockIdx.y * 64, n0 = blockIdx.x * 64;
    const int lrow = tid >> 2;          // 0..63
    const int lcol = (tid & 3) * 4;     // 0,4,8,12

    float acc[4][4] = {};

    for (int k0 = 0; k0 < ND; k0 += 16) {
        float4 a4 = *reinterpret_cast<const float4*>(X + (size_t)(m0 + lrow) * ND + k0 + lcol);
        float4 b4 = *reinterpret_cast<const float4*>(W + (size_t)(n0 + lrow) * ND + k0 + lcol);
        As[lrow][lcol + 0] = a4.x; As[lrow][lcol + 1] = a4.y;
        As[lrow][lcol + 2] = a4.z; As[lrow][lcol + 3] = a4.w;
        Bs[lrow][lcol + 0] = b4.x; Bs[lrow][lcol + 1] = b4.y;
        Bs[lrow][lcol + 2] = b4.z; Bs[lrow][lcol + 3] = b4.w;
        __syncthreads();
#pragma unroll
        for (int k = 0; k < 16; ++k) {
            float a[4], b[4];
#pragma unroll
            for (int i = 0; i < 4; ++i) a[i] = As[ty * 4 + i][k];
#pragma unroll
            for (int j = 0; j < 4; ++j) b[j] = Bs[tx * 4 + j][k];
#pragma unroll
            for (int i = 0; i < 4; ++i)
#pragma unroll
                for (int j = 0; j < 4; ++j) acc[i][j] += a[i] * b[j];
        }
        __syncthreads();
    }

#pragma unroll
    for (int i = 0; i < 4; ++i) {
        const int m = m0 + ty * 4 + i;
#pragma unroll
        for (int j = 0; j < 4; ++j) {
            const int n = n0 + tx * 4 + j;
            if (MODE == 3) {
                outp[(size_t)m * ND + n] = acc[i][j];
            } else {
                const int b = m / NS, s = m % NS;
                const int h = n / NDK, dc = n % NDK;
                float* dst = (MODE == 0) ? g_q : (MODE == 1) ? g_k : g_v;
                dst[(((size_t)b * NH + h) * NS + s) * NDK + dc] = acc[i][j];
            }
        }
    }
}

// ---------------------------------------------------------------------------
// Causal flash attention, fp32, BM=BN=64, dk=64, online softmax.
// Grid: (NS/64, NB*NH). 256 threads, 16x16 thread grid, 4x4 microtiles.
// Skips key blocks beyond the causal frontier (~2x work saving).
// ---------------------------------------------------------------------------
__global__ __launch_bounds__(256) void flash_kernel() {
    extern __shared__ float smx[];
    float* Qs = smx;               // 64 x 65 (padded)
    float* Ks = Qs + 64 * 65;      // 64 x 65 (padded)
    float* Vs = Ks + 64 * 65;      // 64 x 64
    float* Ps = Vs + 64 * 64;      // 64 x 64

    const int tid = threadIdx.x;
    const int tx = tid & 15, ty = tid >> 4;
    const int qb0 = blockIdx.x * 64;
    const int bh = blockIdx.y;

    const float* qp = g_q + (size_t)bh * NS * NDK;
    const float* kp = g_k + (size_t)bh * NS * NDK;
    const float* vp = g_v + (size_t)bh * NS * NDK;

    // Load Q tile, pre-scaled by 1/sqrt(dk) = 0.125
    for (int i = tid; i < 64 * 16; i += 256) {
        int r = i >> 4, c4 = (i & 15) * 4;
        float4 v4 = *reinterpret_cast<const float4*>(qp + (size_t)(qb0 + r) * NDK + c4);
        Qs[r * 65 + c4 + 0] = v4.x * 0.125f;
        Qs[r * 65 + c4 + 1] = v4.y * 0.125f;
        Qs[r * 65 + c4 + 2] = v4.z * 0.125f;
        Qs[r * 65 + c4 + 3] = v4.w * 0.125f;
    }

    float o[4][4] = {};
    float mrow[4], lrow[4];
#pragma unroll
    for (int r = 0; r < 4; ++r) { mrow[r] = -INFINITY; lrow[r] = 0.0f; }

    const int njb = blockIdx.x + 1;  // causal: only key blocks <= query block
    for (int jb = 0; jb < njb; ++jb) {
        __syncthreads();  // protect Ks/Vs/Ps from previous iteration readers
        const int k0 = jb * 64;
        // Load K and V tiles
        for (int i = tid; i < 64 * 16; i += 256) {
            int r = i >> 4, c4 = (i & 15) * 4;
            float4 kv = *reinterpret_cast<const float4*>(kp + (size_t)(k0 + r) * NDK + c4);
            Ks[r * 65 + c4 + 0] = kv.x; Ks[r * 65 + c4 + 1] = kv.y;
            Ks[r * 65 + c4 + 2] = kv.z; Ks[r * 65 + c4 + 3] = kv.w;
            float4 vv = *reinterpret_cast<const float4*>(vp + (size_t)(k0 + r) * NDK + c4);
            *reinterpret_cast<float4*>(Vs + r * 64 + c4) = vv;
        }
        __syncthreads();

        // S = Q @ K^T (pre-scaled)
        float s[4][4] = {};
#pragma unroll 8
        for (int k = 0; k < 64; ++k) {
            float a[4], b[4];
#pragma unroll
            for (int i = 0; i < 4; ++i) a[i] = Qs[(ty * 4 + i) * 65 + k];
#pragma unroll
            for (int j = 0; j < 4; ++j) b[j] = Ks[(tx * 4 + j) * 65 + k];
#pragma unroll
            for (int i = 0; i < 4; ++i)
#pragma unroll
                for (int j = 0; j < 4; ++j) s[i][j] += a[i] * b[j];
        }

        // Causal mask + online softmax (row groups live in 16-lane shfl groups)
        const bool diag = (jb == blockIdx.x);
#pragma unroll
        for (int r = 0; r < 4; ++r) {
            const int qi = qb0 + ty * 4 + r;
            float tmax = -INFINITY;
#pragma unroll
            for (int c = 0; c < 4; ++c) {
                if (diag) {
                    const int kj = k0 + tx * 4 + c;
                    if (kj > qi) s[r][c] = -1e30f;
                }
                tmax = fmaxf(tmax, s[r][c]);
            }
#pragma unroll
            for (int off = 8; off > 0; off >>= 1)
                tmax = fmaxf(tmax, __shfl_xor_sync(0xffffffffu, tmax, off, 16));
            const float mnew = fmaxf(mrow[r], tmax);
            const float scale = __expf(mrow[r] - mnew);
            float rsum = 0.0f;
#pragma unroll
            for (int c = 0; c < 4; ++c) {
                const float p = __expf(s[r][c] - mnew);
                s[r][c] = p;
                rsum += p;
            }
#pragma unroll
            for (int off = 8; off > 0; off >>= 1)
                rsum += __shfl_xor_sync(0xffffffffu, rsum, off, 16);
            lrow[r] = lrow[r] * scale + rsum;
            mrow[r] = mnew;
#pragma unroll
            for (int c = 0; c < 4; ++c) o[r][c] *= scale;
        }

        // Stage P to shared for the PV GEMM
#pragma unroll
        for (int r = 0; r < 4; ++r)
#pragma unroll
            for (int c = 0; c < 4; ++c)
                Ps[(ty * 4 + r) * 64 + tx * 4 + c] = s[r][c];
        __syncthreads();

        // O += P @ V
#pragma unroll 8
        for (int k = 0; k < 64; ++k) {
            float a[4], b[4];
#pragma unroll
            for (int r = 0; r < 4; ++r) a[r] = Ps[(ty * 4 + r) * 64 + k];
#pragma unroll
            for (int c = 0; c < 4; ++c) b[c] = Vs[k * 64 + tx * 4 + c];
#pragma unroll
            for (int r = 0; r < 4; ++r)
#pragma unroll
                for (int c = 0; c < 4; ++c) o[r][c] += a[r] * b[c];
        }
    }

    // Normalize and write ctx in (b, s, d) layout, d = h*64 + col
    const int b = bh / NH, h = bh % NH;
#pragma unroll
    for (int r = 0; r < 4; ++r) {
        const float inv = 1.0f / lrow[r];
        const int srow = qb0 + ty * 4 + r;
#pragma unroll
        for (int c = 0; c < 4; ++c) {
            g_ctx[((size_t)b * NS + srow) * ND + h * NDK + tx * 4 + c] = o[r][c] * inv;
        }
    }
}

// ---------------------------------------------------------------------------
// Launch: 3 projection GEMMs -> flash attention -> output GEMM.
// All on default stream (serialized dependencies), graph-capturable.
// ---------------------------------------------------------------------------
extern "C" void kernel_launch(void* const* d_in, const int* in_sizes, int n_in,
                              void* d_out, int out_size) {
    (void)in_sizes; (void)n_in; (void)out_size;
    const float* Q  = (const float*)d_in[0];
    const float* K  = (const float*)d_in[1];
    const float* V  = (const float*)d_in[2];
    // d_in[3] is the causal mask (tril) -- causality is applied analytically.
    const float* Wq = (const float*)d_in[4];
    const float* Wk = (const float*)d_in[5];
    const float* Wv = (const float*)d_in[6];
    const float* Wo = (const float*)d_in[7];
    float* out = (float*)d_out;

    const dim3 gg(ND / 64, NM / 64);   // (12, 64)
    gemm_xwt<0><<<gg, 256>>>(Q, Wq, nullptr);
    gemm_xwt<1><<<gg, 256>>>(K, Wk, nullptr);
    gemm_xwt<2><<<gg, 256>>>(V, Wv, nullptr);

    const int flash_smem = (2 * 64 * 65 + 2 * 64 * 64) * (int)sizeof(float);  // 66048 B
    cudaFuncSetAttribute(flash_kernel, cudaFuncAttributeMaxDynamicSharedMemorySize, flash_smem);
    flash_kernel<<<dim3(NS / 64, NB * NH), 256, flash_smem>>>();

    gemm_xwt<3><<<gg, 256>>>(nullptr, Wo, out);
}

// round 3
// speedup vs baseline: 2.3927x; 2.3927x over previous
#include <cuda_runtime.h>
#include <math.h>

#define NB 2
#define NS 2048
#define ND 768
#define NH 12
#define NDK 64
#define NM (NB * NS)

// Scratch (static device globals -- no runtime allocation).
__device__ float g_q[(size_t)NB * NH * NS * NDK];
__device__ float g_k[(size_t)NB * NH * NS * NDK];
__device__ float g_v[(size_t)NB * NH * NS * NDK];
__device__ float g_ctx[(size_t)NB * NS * ND];

// ---------------------------------------------------------------------------
// tf32 helpers
// ---------------------------------------------------------------------------
__device__ __forceinline__ float f2tf(float x) {
    unsigned r;
    asm("cvt.rna.tf32.f32 %0, %1;" : "=r"(r) : "f"(x));
    return __uint_as_float(r);
}

__device__ __forceinline__ void mma8(float d[4], const unsigned a[4], const unsigned b[2]) {
    asm volatile(
        "mma.sync.aligned.m16n8k8.row.col.f32.tf32.tf32.f32 "
        "{%0,%1,%2,%3}, {%4,%5,%6,%7}, {%8,%9}, {%0,%1,%2,%3};"
        : "+f"(d[0]), "+f"(d[1]), "+f"(d[2]), "+f"(d[3])
        : "r"(a[0]), "r"(a[1]), "r"(a[2]), "r"(a[3]), "r"(b[0]), "r"(b[1]));
}

// ---------------------------------------------------------------------------
// GEMM: out = X @ W^T via m16n8k8 tf32 MMA.
// Block tile 128x128, 8 warps (2x4), warp tile 64x32, K-tile 32.
// MODE 0/1/2: head-split into g_q/g_k/g_v.  MODE 3: flat into outp.
// ---------------------------------------------------------------------------
template <int MODE>
__global__ __launch_bounds__(256) void gemm_mma(const float* __restrict__ Xin,
                                                const float* __restrict__ W,
                                                float* __restrict__ outp) {
    __shared__ float As[128][36];   // X tile [m][k], tf32-rounded
    __shared__ float Bs[128][36];   // W tile [n][k], tf32-rounded

    const float* X = (MODE == 3) ? g_ctx : Xin;
    const int tid = threadIdx.x;
    const int wid = tid >> 5, lane = tid & 31;
    const int wm = wid >> 2;        // 0..1  (64 rows each)
    const int wn = wid & 3;         // 0..3  (32 cols each)
    const int gq = lane >> 2, gr = lane & 3;
    const int m0 = blockIdx.y * 128, n0 = blockIdx.x * 128;

    float acc[4][4][4] = {};

    for (int k0 = 0; k0 < ND; k0 += 32) {
#pragma unroll
        for (int i = 0; i < 4; ++i) {
            const int slot = tid + i * 256;           // 0..1023
            const int row = slot >> 3, c4 = (slot & 7) * 4;
            float4 xv = *reinterpret_cast<const float4*>(X + (size_t)(m0 + row) * ND + k0 + c4);
            As[row][c4 + 0] = f2tf(xv.x); As[row][c4 + 1] = f2tf(xv.y);
            As[row][c4 + 2] = f2tf(xv.z); As[row][c4 + 3] = f2tf(xv.w);
            float4 wv = *reinterpret_cast<const float4*>(W + (size_t)(n0 + row) * ND + k0 + c4);
            Bs[row][c4 + 0] = f2tf(wv.x); Bs[row][c4 + 1] = f2tf(wv.y);
            Bs[row][c4 + 2] = f2tf(wv.z); Bs[row][c4 + 3] = f2tf(wv.w);
        }
        __syncthreads();
#pragma unroll
        for (int kk = 0; kk < 4; ++kk) {
            const int kb = kk * 8;
            unsigned af[4][4], bf[4][2];
#pragma unroll
            for (int mt = 0; mt < 4; ++mt) {
                const int rb = wm * 64 + mt * 16;
                af[mt][0] = __float_as_uint(As[rb + gq][kb + gr]);
                af[mt][1] = __float_as_uint(As[rb + 8 + gq][kb + gr]);
                af[mt][2] = __float_as_uint(As[rb + gq][kb + gr + 4]);
                af[mt][3] = __float_as_uint(As[rb + 8 + gq][kb + gr + 4]);
            }
#pragma unroll
            for (int nt = 0; nt < 4; ++nt) {
                const int nb = wn * 32 + nt * 8;
                bf[nt][0] = __float_as_uint(Bs[nb + gq][kb + gr]);
                bf[nt][1] = __float_as_uint(Bs[nb + gq][kb + gr + 4]);
            }
#pragma unroll
            for (int mt = 0; mt < 4; ++mt)
#pragma unroll
                for (int nt = 0; nt < 4; ++nt) mma8(acc[mt][nt], af[mt], bf[nt]);
        }
        __syncthreads();
    }

    // Epilogue: D layout c0..c3 = (row,2c),(row,2c+1),(row+8,2c),(row+8,2c+1)
#pragma unroll
    for (int mt = 0; mt < 4; ++mt) {
#pragma unroll
        for (int nt = 0; nt < 4; ++nt) {
#pragma unroll
            for (int half = 0; half < 2; ++half) {
                const int m = m0 + wm * 64 + mt * 16 + gq + half * 8;
                const int ncol = n0 + wn * 32 + nt * 8 + gr * 2;
                const float v0 = acc[mt][nt][half * 2 + 0];
                const float v1 = acc[mt][nt][half * 2 + 1];
                if (MODE == 3) {
                    outp[(size_t)m * ND + ncol] = v0;
                    outp[(size_t)m * ND + ncol + 1] = v1;
                } else {
                    const int b = m / NS, s = m % NS;
                    const int h = ncol / NDK, dc = ncol % NDK;
                    float* dst = (MODE == 0) ? g_q : (MODE == 1) ? g_k : g_v;
                    float* p = dst + (((size_t)b * NH + h) * NS + s) * NDK + dc;
                    p[0] = v0; p[1] = v1;
                }
            }
        }
    }
}

// ---------------------------------------------------------------------------
// Causal flash attention via m16n8k8 tf32 MMA.
// BM=BN=64, dk=64. 128 threads = 4 warps; each warp owns 16 query rows.
// ---------------------------------------------------------------------------
#define QS_STRIDE 68
#define VS_STRIDE 72

__global__ __launch_bounds__(128) void flash_mma() {
    extern __shared__ float smx[];
    float* Qs = smx;                         // 64 x 68
    float* Ks = Qs + 64 * QS_STRIDE;         // 64 x 68
    float* Vs = Ks + 64 * QS_STRIDE;         // 64 x 72  [k][n]
    float* Ps = Vs + 64 * VS_STRIDE;         // 4 x (16 x 68) per-warp

    const int tid = threadIdx.x;
    const int wid = tid >> 5, lane = tid & 31;
    const int gq = lane >> 2, gr = lane & 3;
    const int qb0 = blockIdx.x * 64;
    const int bh = blockIdx.y;

    const float* qp = g_q + (size_t)bh * NS * NDK;
    const float* kp = g_k + (size_t)bh * NS * NDK;
    const float* vp = g_v + (size_t)bh * NS * NDK;
    float* Pw = Ps + wid * 16 * QS_STRIDE;

    // Load Q tile (pre-scaled by 1/8, then tf32-rounded)
#pragma unroll
    for (int i = 0; i < 8; ++i) {
        const int slot = tid + i * 128;            // 0..1023
        const int r = slot >> 4, c4 = (slot & 15) * 4;
        float4 v4 = *reinterpret_cast<const float4*>(qp + (size_t)(qb0 + r) * NDK + c4);
        Qs[r * QS_STRIDE + c4 + 0] = f2tf(v4.x * 0.125f);
        Qs[r * QS_STRIDE + c4 + 1] = f2tf(v4.y * 0.125f);
        Qs[r * QS_STRIDE + c4 + 2] = f2tf(v4.z * 0.125f);
        Qs[r * QS_STRIDE + c4 + 3] = f2tf(v4.w * 0.125f);
    }

    float o[8][4] = {};
    float mrow[2] = {-1e30f, -1e30f};
    float lrow[2] = {0.0f, 0.0f};

    const int njb = blockIdx.x + 1;
    for (int jb = 0; jb < njb; ++jb) {
        __syncthreads();
        const int k0 = jb * 64;
#pragma unroll
        for (int i = 0; i < 8; ++i) {
            const int slot = tid + i * 128;
            const int r = slot >> 4, c4 = (slot & 15) * 4;
            float4 kv = *reinterpret_cast<const float4*>(kp + (size_t)(k0 + r) * NDK + c4);
            Ks[r * QS_STRIDE + c4 + 0] = f2tf(kv.x);
            Ks[r * QS_STRIDE + c4 + 1] = f2tf(kv.y);
            Ks[r * QS_STRIDE + c4 + 2] = f2tf(kv.z);
            Ks[r * QS_STRIDE + c4 + 3] = f2tf(kv.w);
            float4 vv = *reinterpret_cast<const float4*>(vp + (size_t)(k0 + r) * NDK + c4);
            Vs[r * VS_STRIDE + c4 + 0] = f2tf(vv.x);
            Vs[r * VS_STRIDE + c4 + 1] = f2tf(vv.y);
            Vs[r * VS_STRIDE + c4 + 2] = f2tf(vv.z);
            Vs[r * VS_STRIDE + c4 + 3] = f2tf(vv.w);
        }
        __syncthreads();

        // S = Qtile @ K^T   (warp rows: wid*16 .. +16, cols 0..63)
        float s[8][4] = {};
        const int rb = wid * 16;
#pragma unroll
        for (int kk = 0; kk < 8; ++kk) {
            const int kb = kk * 8;
            unsigned af[4];
            af[0] = __float_as_uint(Qs[(rb + gq) * QS_STRIDE + kb + gr]);
            af[1] = __float_as_uint(Qs[(rb + 8 + gq) * QS_STRIDE + kb + gr]);
            af[2] = __float_as_uint(Qs[(rb + gq) * QS_STRIDE + kb + gr + 4]);
            af[3] = __float_as_uint(Qs[(rb + 8 + gq) * QS_STRIDE + kb + gr + 4]);
#pragma unroll
            for (int nt = 0; nt < 8; ++nt) {
                unsigned bf[2];
                bf[0] = __float_as_uint(Ks[(nt * 8 + gq) * QS_STRIDE + kb + gr]);
                bf[1] = __float_as_uint(Ks[(nt * 8 + gq) * QS_STRIDE + kb + gr + 4]);
                mma8(s[nt], af, bf);
            }
        }

        // Causal mask + online softmax. Thread rows: qi0 = qb0+rb+gq, qi1 = +8.
        const bool diag = (jb == blockIdx.x);
        if (diag) {
            const int qi0 = qb0 + rb + gq;
#pragma unroll
            for (int nt = 0; nt < 8; ++nt) {
                const int kj = k0 + nt * 8 + gr * 2;
                if (kj > qi0) s[nt][0] = -1e30f;
                if (kj + 1 > qi0) s[nt][1] = -1e30f;
                if (kj > qi0 + 8) s[nt][2] = -1e30f;
                if (kj + 1 > qi0 + 8) s[nt][3] = -1e30f;
            }
        }
#pragma unroll
        for (int half = 0; half < 2; ++half) {
            float tmax = -1e30f;
#pragma unroll
            for (int nt = 0; nt < 8; ++nt)
                tmax = fmaxf(tmax, fmaxf(s[nt][half * 2], s[nt][half * 2 + 1]));
            tmax = fmaxf(tmax, __shfl_xor_sync(0xffffffffu, tmax, 1));
            tmax = fmaxf(tmax, __shfl_xor_sync(0xffffffffu, tmax, 2));
            const float mnew = fmaxf(mrow[half], tmax);
            const float scl = __expf(mrow[half] - mnew);
            float rsum = 0.0f;
#pragma unroll
            for (int nt = 0; nt < 8; ++nt) {
                const float p0 = __expf(s[nt][half * 2] - mnew);
                const float p1 = __expf(s[nt][half * 2 + 1] - mnew);
                s[nt][half * 2] = p0; s[nt][half * 2 + 1] = p1;
                rsum += p0 + p1;
            }
            rsum += __shfl_xor_sync(0xffffffffu, rsum, 1);
            rsum += __shfl_xor_sync(0xffffffffu, rsum, 2);
            lrow[half] = lrow[half] * scl + rsum;
            mrow[half] = mnew;
#pragma unroll
            for (int nt = 0; nt < 8; ++nt) {
                o[nt][half * 2] *= scl;
                o[nt][half * 2 + 1] *= scl;
            }
        }

        // Stage P (tf32-rounded) into per-warp smem region
#pragma unroll
        for (int nt = 0; nt < 8; ++nt) {
            const int cc = nt * 8 + gr * 2;
            Pw[gq * QS_STRIDE + cc] = f2tf(s[nt][0]);
            Pw[gq * QS_STRIDE + cc + 1] = f2tf(s[nt][1]);
            Pw[(gq + 8) * QS_STRIDE + cc] = f2tf(s[nt][2]);
            Pw[(gq + 8) * QS_STRIDE + cc + 1] = f2tf(s[nt][3]);
        }
        __syncwarp();

        // O += P @ V
#pragma unroll
        for (int kk = 0; kk < 8; ++kk) {
            const int kb = kk * 8;
            unsigned af[4];
            af[0] = __float_as_uint(Pw[gq * QS_STRIDE + kb + gr]);
            af[1] = __float_as_uint(Pw[(gq + 8) * QS_STRIDE + kb + gr]);
            af[2] = __float_as_uint(Pw[gq * QS_STRIDE + kb + gr + 4]);
            af[3] = __float_as_uint(Pw[(gq + 8) * QS_STRIDE + kb + gr + 4]);
#pragma unroll
            for (int nt = 0; nt < 8; ++nt) {
                unsigned bf[2];
                bf[0] = __float_as_uint(Vs[(kb + gr) * VS_STRIDE + nt * 8 + gq]);
                bf[1] = __float_as_uint(Vs[(kb + gr + 4) * VS_STRIDE + nt * 8 + gq]);
                mma8(o[nt], af, bf);
            }
        }
        __syncwarp();
    }

    // Normalize, write ctx in (b, s, d) layout
    const int b = bh / NH, h = bh % NH;
    const float inv0 = 1.0f / lrow[0], inv1 = 1.0f / lrow[1];
    const int s0 = qb0 + wid * 16 + gq;
#pragma unroll
    for (int nt = 0; nt < 8; ++nt) {
        const int dc = h * NDK + nt * 8 + gr * 2;
        float* p0 = g_ctx + ((size_t)b * NS + s0) * ND + dc;
        float* p1 = g_ctx + ((size_t)b * NS + s0 + 8) * ND + dc;
        p0[0] = o[nt][0] * inv0; p0[1] = o[nt][1] * inv0;
        p1[0] = o[nt][2] * inv1; p1[1] = o[nt][3] * inv1;
    }
}

// ---------------------------------------------------------------------------
extern "C" void kernel_launch(void* const* d_in, const int* in_sizes, int n_in,
                              void* d_out, int out_size) {
    (void)in_sizes; (void)n_in; (void)out_size;
    const float* Q  = (const float*)d_in[0];
    const float* K  = (const float*)d_in[1];
    const float* V  = (const float*)d_in[2];
    const float* Wq = (const float*)d_in[4];
    const float* Wk = (const float*)d_in[5];
    const float* Wv = (const float*)d_in[6];
    const float* Wo = (const float*)d_in[7];
    float* out = (float*)d_out;

    const dim3 gg(ND / 128, NM / 128);   // (6, 32)
    gemm_mma<0><<<gg, 256>>>(Q, Wq, nullptr);
    gemm_mma<1><<<gg, 256>>>(K, Wk, nullptr);
    gemm_mma<2><<<gg, 256>>>(V, Wv, nullptr);

    const int flash_smem = (2 * 64 * QS_STRIDE + 64 * VS_STRIDE + 4 * 16 * QS_STRIDE) * (int)sizeof(float);
    cudaFuncSetAttribute(flash_mma, cudaFuncAttributeMaxDynamicSharedMemorySize, flash_smem);
    flash_mma<<<dim3(NS / 64, NB * NH), 128, flash_smem>>>();

    gemm_mma<3><<<gg, 256>>>(nullptr, Wo, out);
}

// round 6
// speedup vs baseline: 3.2273x; 1.3488x over previous
#include <cuda_runtime.h>
#include <math.h>

#define NB 2
#define NS 2048
#define ND 768
#define NH 12
#define NDK 64
#define NM (NB * NS)

// Scratch (static device globals -- no runtime allocation).
// g_q/g_k/g_v hold tf32-ROUNDED values (g_q also pre-scaled by 1/8).
__device__ float g_q[(size_t)NB * NH * NS * NDK];
__device__ float g_k[(size_t)NB * NH * NS * NDK];
__device__ float g_v[(size_t)NB * NH * NS * NDK];
__device__ float g_ctx[(size_t)NB * NS * ND];   // tf32-rounded ctx

// ---------------------------------------------------------------------------
__device__ __forceinline__ float f2tf(float x) {
    unsigned r;
    asm("cvt.rna.tf32.f32 %0, %1;" : "=r"(r) : "f"(x));
    return __uint_as_float(r);
}

__device__ __forceinline__ void mma8(float d[4], const unsigned a[4], const unsigned b[2]) {
    asm volatile(
        "mma.sync.aligned.m16n8k8.row.col.f32.tf32.tf32.f32 "
        "{%0,%1,%2,%3}, {%4,%5,%6,%7}, {%8,%9}, {%0,%1,%2,%3};"
        : "+f"(d[0]), "+f"(d[1]), "+f"(d[2]), "+f"(d[3])
        : "r"(a[0]), "r"(a[1]), "r"(a[2]), "r"(a[3]), "r"(b[0]), "r"(b[1]));
}

__device__ __forceinline__ unsigned smem_u32(const void* p) {
    return (unsigned)__cvta_generic_to_shared(p);
}
__device__ __forceinline__ void cp16(unsigned s, const void* g) {
    asm volatile("cp.async.cg.shared.global [%0], [%1], 16;" :: "r"(s), "l"(g));
}
__device__ __forceinline__ void cp_commit() {
    asm volatile("cp.async.commit_group;" ::: "memory");
}
template <int N>
__device__ __forceinline__ void cp_wait() {
    asm volatile("cp.async.wait_group %0;" :: "n"(N) : "memory");
}

// ---------------------------------------------------------------------------
// GEMM: out = X @ W^T via m16n8k8 tf32 MMA.
// Block tile 128x64, 128 threads (4 warps, 2x2 warp grid, warp tile 64x32).
// FINAL=0: grid.z selects Q/K/V; epilogue stores tf32-rounded (Q also *0.125)
//          head-split into g_q/g_k/g_v.
// FINAL=1: X = g_ctx, W = Wo, flat fp32 store into outp.
// ---------------------------------------------------------------------------
template <int FINAL>
__global__ __launch_bounds__(128) void gemm_mma(const float* __restrict__ X0,
                                                const float* __restrict__ X1,
                                                const float* __restrict__ X2,
                                                const float* __restrict__ W0,
                                                const float* __restrict__ W1,
                                                const float* __restrict__ W2,
                                                float* __restrict__ outp) {
    __shared__ float As[128][36];   // X tile [m][k], tf32-rounded
    __shared__ float Bs[64][36];    // W tile [n][k], tf32-rounded

    const int z = FINAL ? 0 : blockIdx.z;
    const float* X = FINAL ? g_ctx : (z == 0 ? X0 : (z == 1 ? X1 : X2));
    const float* W = FINAL ? W0 : (z == 0 ? W0 : (z == 1 ? W1 : W2));

    const int tid = threadIdx.x;
    const int wid = tid >> 5, lane = tid & 31;
    const int wm = wid >> 1;        // 0..1  (64 rows each)
    const int wn = wid & 1;         // 0..1  (32 cols each)
    const int gq = lane >> 2, gr = lane & 3;
    const int m0 = blockIdx.y * 128, n0 = blockIdx.x * 64;

    float acc[4][4][4] = {};

    for (int k0 = 0; k0 < ND; k0 += 32) {
#pragma unroll
        for (int i = 0; i < 8; ++i) {
            const int slot = tid + i * 128;           // 0..1023
            const int row = slot >> 3, c4 = (slot & 7) * 4;
            float4 xv = *reinterpret_cast<const float4*>(X + (size_t)(m0 + row) * ND + k0 + c4);
            As[row][c4 + 0] = f2tf(xv.x); As[row][c4 + 1] = f2tf(xv.y);
            As[row][c4 + 2] = f2tf(xv.z); As[row][c4 + 3] = f2tf(xv.w);
        }
#pragma unroll
        for (int i = 0; i < 4; ++i) {
            const int slot = tid + i * 128;           // 0..511
            const int row = slot >> 3, c4 = (slot & 7) * 4;
            float4 wv = *reinterpret_cast<const float4*>(W + (size_t)(n0 + row) * ND + k0 + c4);
            Bs[row][c4 + 0] = f2tf(wv.x); Bs[row][c4 + 1] = f2tf(wv.y);
            Bs[row][c4 + 2] = f2tf(wv.z); Bs[row][c4 + 3] = f2tf(wv.w);
        }
        __syncthreads();
#pragma unroll
        for (int kk = 0; kk < 4; ++kk) {
            const int kb = kk * 8;
            unsigned af[4][4], bf[4][2];
#pragma unroll
            for (int mt = 0; mt < 4; ++mt) {
                const int rb = wm * 64 + mt * 16;
                af[mt][0] = __float_as_uint(As[rb + gq][kb + gr]);
                af[mt][1] = __float_as_uint(As[rb + 8 + gq][kb + gr]);
                af[mt][2] = __float_as_uint(As[rb + gq][kb + gr + 4]);
                af[mt][3] = __float_as_uint(As[rb + 8 + gq][kb + gr + 4]);
            }
#pragma unroll
            for (int nt = 0; nt < 4; ++nt) {
                const int nb = wn * 32 + nt * 8;
                bf[nt][0] = __float_as_uint(Bs[nb + gq][kb + gr]);
                bf[nt][1] = __float_as_uint(Bs[nb + gq][kb + gr + 4]);
            }
#pragma unroll
            for (int mt = 0; mt < 4; ++mt)
#pragma unroll
                for (int nt = 0; nt < 4; ++nt) mma8(acc[mt][nt], af[mt], bf[nt]);
        }
        __syncthreads();
    }

    float* dst = FINAL ? outp : (z == 0 ? g_q : (z == 1 ? g_k : g_v));
    const float escl = (!FINAL && z == 0) ? 0.125f : 1.0f;
#pragma unroll
    for (int mt = 0; mt < 4; ++mt) {
#pragma unroll
        for (int nt = 0; nt < 4; ++nt) {
#pragma unroll
            for (int half = 0; half < 2; ++half) {
                const int m = m0 + wm * 64 + mt * 16 + gq + half * 8;
                const int ncol = n0 + wn * 32 + nt * 8 + gr * 2;
                const float v0 = acc[mt][nt][half * 2 + 0];
                const float v1 = acc[mt][nt][half * 2 + 1];
                if (FINAL) {
                    dst[(size_t)m * ND + ncol] = v0;
                    dst[(size_t)m * ND + ncol + 1] = v1;
                } else {
                    const int b = m >> 11, s = m & (NS - 1);
                    const int h = ncol >> 6, dc = ncol & 63;
                    float* p = dst + (((size_t)b * NH + h) * NS + s) * NDK + dc;
                    p[0] = f2tf(v0 * escl);
                    p[1] = f2tf(v1 * escl);
                }
            }
        }
    }
}

// ---------------------------------------------------------------------------
// Causal flash attention via m16n8k8 tf32 MMA.
// BM=64, BN=64, dk=64. 128 threads = 4 warps; warp owns 16 query rows.
// Q kept in registers (pre-rounded + pre-scaled by GEMM epilogue).
// K/V double-buffered via cp.async 2-stage pipeline.
// ---------------------------------------------------------------------------
#define KS_STRIDE 68
#define VS_STRIDE 72
#define KV_BUF (64 * KS_STRIDE + 64 * VS_STRIDE)
#define FLASH_SMEM ((2 * KV_BUF + 4 * 16 * KS_STRIDE) * 4)

__global__ __launch_bounds__(128) void flash_mma() {
    extern __shared__ float smx[];
    // Two K/V stages, then per-warp P staging.
    float* Ps = smx + 2 * KV_BUF;            // 4 x (16 x 68)

    const int tid = threadIdx.x;
    const int wid = tid >> 5, lane = tid & 31;
    const int gq = lane >> 2, gr = lane & 3;
    const int qb0 = blockIdx.x * 64;
    const int bh = blockIdx.y;
    const int rb = wid * 16;

    const float* qp = g_q + (size_t)bh * NS * NDK;
    const float* kp = g_k + (size_t)bh * NS * NDK;
    const float* vp = g_v + (size_t)bh * NS * NDK;
    float* Pw = Ps + wid * 16 * KS_STRIDE;

    // Per-thread row/chunk for the cp.async loads (4 iters x 128 threads = 512 slots)
    // slot -> row (0..63), chunk c8 (0..56 step 8)

    // Q fragments straight from global into registers
    unsigned qf[8][4];
#pragma unroll
    for (int kk = 0; kk < 8; ++kk) {
        const int kb = kk * 8;
        qf[kk][0] = __float_as_uint(qp[(size_t)(qb0 + rb + gq) * NDK + kb + gr]);
        qf[kk][1] = __float_as_uint(qp[(size_t)(qb0 + rb + 8 + gq) * NDK + kb + gr]);
        qf[kk][2] = __float_as_uint(qp[(size_t)(qb0 + rb + gq) * NDK + kb + gr + 4]);
        qf[kk][3] = __float_as_uint(qp[(size_t)(qb0 + rb + 8 + gq) * NDK + kb + gr + 4]);
    }

    float o[8][4] = {};
    float mrow[2] = {-1e30f, -1e30f};
    float lrow[2] = {0.0f, 0.0f};

    const int njb = blockIdx.x + 1;

    // Issue prefetch of tile 0 into stage 0.
    {
        float* Kb = smx;                     // stage 0
        float* Vb = smx + 64 * KS_STRIDE;
#pragma unroll
        for (int i = 0; i < 4; ++i) {
            const int slot = tid + i * 128;
            const int r = slot >> 3, c8 = (slot & 7) * 8;
            cp16(smem_u32(Kb + r * KS_STRIDE + c8), kp + (size_t)r * NDK + c8);
            cp16(smem_u32(Kb + r * KS_STRIDE + c8 + 4), kp + (size_t)r * NDK + c8 + 4);
            cp16(smem_u32(Vb + r * VS_STRIDE + c8), vp + (size_t)r * NDK + c8);
            cp16(smem_u32(Vb + r * VS_STRIDE + c8 + 4), vp + (size_t)r * NDK + c8 + 4);
        }
        cp_commit();
    }

    for (int jb = 0; jb < njb; ++jb) {
        const int cur = jb & 1;
        float* Ks = smx + cur * KV_BUF;
        float* Vs = Ks + 64 * KS_STRIDE;

        // All warps done reading buffer cur^1 (compute of jb-1) before refilling it.
        __syncthreads();
        if (jb + 1 < njb) {
            const int kn = (jb + 1) * 64;
            float* Kb = smx + (cur ^ 1) * KV_BUF;
            float* Vb = Kb + 64 * KS_STRIDE;
#pragma unroll
            for (int i = 0; i < 4; ++i) {
                const int slot = tid + i * 128;
                const int r = slot >> 3, c8 = (slot & 7) * 8;
                cp16(smem_u32(Kb + r * KS_STRIDE + c8), kp + (size_t)(kn + r) * NDK + c8);
                cp16(smem_u32(Kb + r * KS_STRIDE + c8 + 4), kp + (size_t)(kn + r) * NDK + c8 + 4);
                cp16(smem_u32(Vb + r * VS_STRIDE + c8), vp + (size_t)(kn + r) * NDK + c8);
                cp16(smem_u32(Vb + r * VS_STRIDE + c8 + 4), vp + (size_t)(kn + r) * NDK + c8 + 4);
            }
            cp_commit();
            cp_wait<1>();   // current tile (older group) complete; prefetch in flight
        } else {
            cp_wait<0>();
        }
        __syncthreads();

        // S = Qtile @ K^T
        float s[8][4] = {};
#pragma unroll
        for (int kk = 0; kk < 8; ++kk) {
            const int kb = kk * 8;
#pragma unroll
            for (int nt = 0; nt < 8; ++nt) {
                unsigned bf[2];
                bf[0] = __float_as_uint(Ks[(nt * 8 + gq) * KS_STRIDE + kb + gr]);
                bf[1] = __float_as_uint(Ks[(nt * 8 + gq) * KS_STRIDE + kb + gr + 4]);
                mma8(s[nt], qf[kk], bf);
            }
        }

        // Causal mask + online softmax
        const int k0 = jb * 64;
        const bool diag = (jb == blockIdx.x);
        if (diag) {
            const int qi0 = qb0 + rb + gq;
#pragma unroll
            for (int nt = 0; nt < 8; ++nt) {
                const int kj = k0 + nt * 8 + gr * 2;
                if (kj > qi0) s[nt][0] = -1e30f;
                if (kj + 1 > qi0) s[nt][1] = -1e30f;
                if (kj > qi0 + 8) s[nt][2] = -1e30f;
                if (kj + 1 > qi0 + 8) s[nt][3] = -1e30f;
            }
        }
#pragma unroll
        for (int half = 0; half < 2; ++half) {
            float tmax = -1e30f;
#pragma unroll
            for (int nt = 0; nt < 8; ++nt)
                tmax = fmaxf(tmax, fmaxf(s[nt][half * 2], s[nt][half * 2 + 1]));
            tmax = fmaxf(tmax, __shfl_xor_sync(0xffffffffu, tmax, 1));
            tmax = fmaxf(tmax, __shfl_xor_sync(0xffffffffu, tmax, 2));
            const float mnew = fmaxf(mrow[half], tmax);
            const float scl = __expf(mrow[half] - mnew);
            float rsum = 0.0f;
#pragma unroll
            for (int nt = 0; nt < 8; ++nt) {
                const float p0 = __expf(s[nt][half * 2] - mnew);
                const float p1 = __expf(s[nt][half * 2 + 1] - mnew);
                s[nt][half * 2] = p0; s[nt][half * 2 + 1] = p1;
                rsum += p0 + p1;
            }
            rsum += __shfl_xor_sync(0xffffffffu, rsum, 1);
            rsum += __shfl_xor_sync(0xffffffffu, rsum, 2);
            lrow[half] = lrow[half] * scl + rsum;
            mrow[half] = mnew;
#pragma unroll
            for (int nt = 0; nt < 8; ++nt) {
                o[nt][half * 2] *= scl;
                o[nt][half * 2 + 1] *= scl;
            }
        }

        // Stage P (tf32-rounded) into per-warp smem region
#pragma unroll
        for (int nt = 0; nt < 8; ++nt) {
            const int cc = nt * 8 + gr * 2;
            Pw[gq * KS_STRIDE + cc] = f2tf(s[nt][0]);
            Pw[gq * KS_STRIDE + cc + 1] = f2tf(s[nt][1]);
            Pw[(gq + 8) * KS_STRIDE + cc] = f2tf(s[nt][2]);
            Pw[(gq + 8) * KS_STRIDE + cc + 1] = f2tf(s[nt][3]);
        }
        __syncwarp();

        // O += P @ V
#pragma unroll
        for (int kk = 0; kk < 8; ++kk) {
            const int kb = kk * 8;
            unsigned af[4];
            af[0] = __float_as_uint(Pw[gq * KS_STRIDE + kb + gr]);
            af[1] = __float_as_uint(Pw[(gq + 8) * KS_STRIDE + kb + gr]);
            af[2] = __float_as_uint(Pw[gq * KS_STRIDE + kb + gr + 4]);
            af[3] = __float_as_uint(Pw[(gq + 8) * KS_STRIDE + kb + gr + 4]);
#pragma unroll
            for (int nt = 0; nt < 8; ++nt) {
                unsigned bf[2];
                bf[0] = __float_as_uint(Vs[(kb + gr) * VS_STRIDE + nt * 8 + gq]);
                bf[1] = __float_as_uint(Vs[(kb + gr + 4) * VS_STRIDE + nt * 8 + gq]);
                mma8(o[nt], af, bf);
            }
        }
        __syncwarp();
    }

    // Normalize, write ctx tf32-rounded (consumed by out-projection MMA)
    const int b = bh / NH, h = bh % NH;
    const float inv0 = 1.0f / lrow[0], inv1 = 1.0f / lrow[1];
    const int s0 = qb0 + rb + gq;
#pragma unroll
    for (int nt = 0; nt < 8; ++nt) {
        const int dc = h * NDK + nt * 8 + gr * 2;
        float* p0 = g_ctx + ((size_t)b * NS + s0) * ND + dc;
        float* p1 = g_ctx + ((size_t)b * NS + s0 + 8) * ND + dc;
        p0[0] = f2tf(o[nt][0] * inv0); p0[1] = f2tf(o[nt][1] * inv0);
        p1[0] = f2tf(o[nt][2] * inv1); p1[1] = f2tf(o[nt][3] * inv1);
    }
}

// ---------------------------------------------------------------------------
extern "C" void kernel_launch(void* const* d_in, const int* in_sizes, int n_in,
                              void* d_out, int out_size) {
    (void)in_sizes; (void)n_in; (void)out_size;
    const float* Q  = (const float*)d_in[0];
    const float* K  = (const float*)d_in[1];
    const float* V  = (const float*)d_in[2];
    const float* Wq = (const float*)d_in[4];
    const float* Wk = (const float*)d_in[5];
    const float* Wv = (const float*)d_in[6];
    const float* Wo = (const float*)d_in[7];
    float* out = (float*)d_out;

    // Merged Q/K/V projection: one launch, 1152 blocks.
    gemm_mma<0><<<dim3(ND / 64, NM / 128, 3), 128>>>(Q, K, V, Wq, Wk, Wv, nullptr);

    cudaFuncSetAttribute(flash_mma, cudaFuncAttributeMaxDynamicSharedMemorySize, FLASH_SMEM);
    flash_mma<<<dim3(NS / 64, NB * NH), 128, FLASH_SMEM>>>();

    // Output projection: 384 blocks.
    gemm_mma<1><<<dim3(ND / 64, NM / 128, 1), 128>>>(nullptr, nullptr, nullptr,
                                                     Wo, nullptr, nullptr, out);
}

// round 8
// speedup vs baseline: 3.5766x; 1.1082x over previous
#include <cuda_runtime.h>
#include <math.h>

#define NB 2
#define NS 2048
#define ND 768
#define NH 12
#define NDK 64
#define NM (NB * NS)

// Scratch (static device globals -- no runtime allocation).
// g_q/g_k/g_v hold tf32-ROUNDED values (g_q also pre-scaled by 1/8).
__device__ float g_q[(size_t)NB * NH * NS * NDK];
__device__ float g_k[(size_t)NB * NH * NS * NDK];
__device__ float g_v[(size_t)NB * NH * NS * NDK];
__device__ float g_ctx[(size_t)NB * NS * ND];   // tf32-rounded ctx

// ---------------------------------------------------------------------------
__device__ __forceinline__ float f2tf(float x) {
    unsigned r;
    asm("cvt.rna.tf32.f32 %0, %1;" : "=r"(r) : "f"(x));
    return __uint_as_float(r);
}
__device__ __forceinline__ unsigned f2tfu(float x) {
    unsigned r;
    asm("cvt.rna.tf32.f32 %0, %1;" : "=r"(r) : "f"(x));
    return r;
}

__device__ __forceinline__ void mma8(float d[4], const unsigned a[4], const unsigned b[2]) {
    asm volatile(
        "mma.sync.aligned.m16n8k8.row.col.f32.tf32.tf32.f32 "
        "{%0,%1,%2,%3}, {%4,%5,%6,%7}, {%8,%9}, {%0,%1,%2,%3};"
        : "+f"(d[0]), "+f"(d[1]), "+f"(d[2]), "+f"(d[3])
        : "r"(a[0]), "r"(a[1]), "r"(a[2]), "r"(a[3]), "r"(b[0]), "r"(b[1]));
}

__device__ __forceinline__ unsigned smem_u32(const void* p) {
    return (unsigned)__cvta_generic_to_shared(p);
}
__device__ __forceinline__ void cp16(unsigned s, const void* g) {
    asm volatile("cp.async.cg.shared.global [%0], [%1], 16;" :: "r"(s), "l"(g));
}
__device__ __forceinline__ void cp_commit() {
    asm volatile("cp.async.commit_group;" ::: "memory");
}
template <int N>
__device__ __forceinline__ void cp_wait() {
    asm volatile("cp.async.wait_group %0;" :: "n"(N) : "memory");
}

// ---------------------------------------------------------------------------
// GEMM: out = X @ W^T via m16n8k8 tf32 MMA.
// Block tile 128x64, 128 threads (4 warps, 2x2 warp grid, warp tile 64x32).
// cp.async double-buffered k-loop (raw fp32 in smem); tf32 rounding applied
// on fragment load (identical numerics to rounding before store).
// FINAL=0: grid.z selects Q/K/V; epilogue stores tf32-rounded (Q also *0.125)
//          head-split into g_q/g_k/g_v.
// FINAL=1: X = g_ctx, W = Wo, flat fp32 store into outp.
// ---------------------------------------------------------------------------
#define NKT (ND / 32)   // 24 k-tiles

template <int FINAL>
__global__ __launch_bounds__(128, 4) void gemm_mma(const float* __restrict__ X0,
                                                   const float* __restrict__ X1,
                                                   const float* __restrict__ X2,
                                                   const float* __restrict__ W0,
                                                   const float* __restrict__ W1,
                                                   const float* __restrict__ W2,
                                                   float* __restrict__ outp) {
    __shared__ float As[2][128][36];   // X tile [m][k], raw fp32
    __shared__ float Bs[2][64][36];    // W tile [n][k], raw fp32

    const int z = FINAL ? 0 : blockIdx.z;
    const float* X = FINAL ? g_ctx : (z == 0 ? X0 : (z == 1 ? X1 : X2));
    const float* W = FINAL ? W0 : (z == 0 ? W0 : (z == 1 ? W1 : W2));

    const int tid = threadIdx.x;
    const int wid = tid >> 5, lane = tid & 31;
    const int wm = wid >> 1;        // 0..1  (64 rows each)
    const int wn = wid & 1;         // 0..1  (32 cols each)
    const int gq = lane >> 2, gr = lane & 3;
    const int m0 = blockIdx.y * 128, n0 = blockIdx.x * 64;

    // cp.async slot mapping (per buffer fill):
    //   As: 8 chunks/thread, Bs: 4 chunks/thread; chunk = 16B.
    float acc[4][4][4] = {};

    // Prefetch k-tile 0 into buffer 0.
    {
#pragma unroll
        for (int i = 0; i < 8; ++i) {
            const int slot = tid + i * 128;                 // 0..1023
            const int row = slot >> 3, c = (slot & 7) * 4;
            cp16(smem_u32(&As[0][row][c]), X + (size_t)(m0 + row) * ND + c);
        }
#pragma unroll
        for (int i = 0; i < 4; ++i) {
            const int slot = tid + i * 128;                 // 0..511
            const int row = slot >> 3, c = (slot & 7) * 4;
            cp16(smem_u32(&Bs[0][row][c]), W + (size_t)(n0 + row) * ND + c);
        }
        cp_commit();
    }

    for (int t = 0; t < NKT; ++t) {
        const int cur = t & 1;
        __syncthreads();   // all warps done reading buffer cur^1 (iter t-1)
        if (t + 1 < NKT) {
            const int kn = (t + 1) * 32;
#pragma unroll
            for (int i = 0; i < 8; ++i) {
                const int slot = tid + i * 128;
                const int row = slot >> 3, c = (slot & 7) * 4;
                cp16(smem_u32(&As[cur ^ 1][row][c]), X + (size_t)(m0 + row) * ND + kn + c);
            }
#pragma unroll
            for (int i = 0; i < 4; ++i) {
                const int slot = tid + i * 128;
                const int row = slot >> 3, c = (slot & 7) * 4;
                cp16(smem_u32(&Bs[cur ^ 1][row][c]), W + (size_t)(n0 + row) * ND + kn + c);
            }
            cp_commit();
            cp_wait<1>();   // tile t complete; prefetch t+1 in flight
        } else {
            cp_wait<0>();
        }
        __syncthreads();

        const float (*Ac)[36] = As[cur];
        const float (*Bc)[36] = Bs[cur];
#pragma unroll
        for (int kk = 0; kk < 4; ++kk) {
            const int kb = kk * 8;
            unsigned af[4][4], bf[4][2];
#pragma unroll
            for (int mt = 0; mt < 4; ++mt) {
                const int rb = wm * 64 + mt * 16;
                af[mt][0] = f2tfu(Ac[rb + gq][kb + gr]);
                af[mt][1] = f2tfu(Ac[rb + 8 + gq][kb + gr]);
                af[mt][2] = f2tfu(Ac[rb + gq][kb + gr + 4]);
                af[mt][3] = f2tfu(Ac[rb + 8 + gq][kb + gr + 4]);
            }
#pragma unroll
            for (int nt = 0; nt < 4; ++nt) {
                const int nb = wn * 32 + nt * 8;
                bf[nt][0] = f2tfu(Bc[nb + gq][kb + gr]);
                bf[nt][1] = f2tfu(Bc[nb + gq][kb + gr + 4]);
            }
#pragma unroll
            for (int mt = 0; mt < 4; ++mt)
#pragma unroll
                for (int nt = 0; nt < 4; ++nt) mma8(acc[mt][nt], af[mt], bf[nt]);
        }
    }

    float* dst = FINAL ? outp : (z == 0 ? g_q : (z == 1 ? g_k : g_v));
    const float escl = (!FINAL && z == 0) ? 0.125f : 1.0f;
#pragma unroll
    for (int mt = 0; mt < 4; ++mt) {
#pragma unroll
        for (int nt = 0; nt < 4; ++nt) {
#pragma unroll
            for (int half = 0; half < 2; ++half) {
                const int m = m0 + wm * 64 + mt * 16 + gq + half * 8;
                const int ncol = n0 + wn * 32 + nt * 8 + gr * 2;
                const float v0 = acc[mt][nt][half * 2 + 0];
                const float v1 = acc[mt][nt][half * 2 + 1];
                if (FINAL) {
                    dst[(size_t)m * ND + ncol] = v0;
                    dst[(size_t)m * ND + ncol + 1] = v1;
                } else {
                    const int b = m >> 11, s = m & (NS - 1);
                    const int h = ncol >> 6, dc = ncol & 63;
                    float* p = dst + (((size_t)b * NH + h) * NS + s) * NDK + dc;
                    p[0] = f2tf(v0 * escl);
                    p[1] = f2tf(v1 * escl);
                }
            }
        }
    }
}

// ---------------------------------------------------------------------------
// Causal flash attention via m16n8k8 tf32 MMA.
// BM=128, BN=64, dk=64. 256 threads = 8 warps; warp owns 16 query rows.
// Q kept in registers (pre-rounded + pre-scaled by GEMM epilogue).
// K/V double-buffered via cp.async 2-stage pipeline.
// ---------------------------------------------------------------------------
#define KS_STRIDE 68
#define VS_STRIDE 72
#define KV_BUF (64 * KS_STRIDE + 64 * VS_STRIDE)
#define FLASH_SMEM ((2 * KV_BUF + 8 * 16 * KS_STRIDE) * 4)

__global__ __launch_bounds__(256, 2) void flash_mma() {
    extern __shared__ float smx[];
    float* Ps = smx + 2 * KV_BUF;            // 8 x (16 x 68) per-warp P staging

    const int tid = threadIdx.x;
    const int wid = tid >> 5, lane = tid & 31;
    const int gq = lane >> 2, gr = lane & 3;
    const int qb0 = blockIdx.x * 128;
    const int bh = blockIdx.y;
    const int rb = wid * 16;                 // warp's query rows [rb, rb+16)

    const float* qp = g_q + (size_t)bh * NS * NDK;
    const float* kp = g_k + (size_t)bh * NS * NDK;
    const float* vp = g_v + (size_t)bh * NS * NDK;
    float* Pw = Ps + wid * 16 * KS_STRIDE;

    // Q fragments straight from global into registers
    unsigned qf[8][4];
#pragma unroll
    for (int kk = 0; kk < 8; ++kk) {
        const int kb = kk * 8;
        qf[kk][0] = __float_as_uint(qp[(size_t)(qb0 + rb + gq) * NDK + kb + gr]);
        qf[kk][1] = __float_as_uint(qp[(size_t)(qb0 + rb + 8 + gq) * NDK + kb + gr]);
        qf[kk][2] = __float_as_uint(qp[(size_t)(qb0 + rb + gq) * NDK + kb + gr + 4]);
        qf[kk][3] = __float_as_uint(qp[(size_t)(qb0 + rb + 8 + gq) * NDK + kb + gr + 4]);
    }

    float o[8][4] = {};
    float mrow[2] = {-1e30f, -1e30f};
    float lrow[2] = {0.0f, 0.0f};

    const int njb = 2 * blockIdx.x + 2;      // key tiles covering rows < qb0+128

    // Prefetch tile 0 into stage 0. 512 slots over 256 threads = 2 iters.
    {
        float* Kb = smx;
        float* Vb = smx + 64 * KS_STRIDE;
#pragma unroll
        for (int i = 0; i < 2; ++i) {
            const int slot = tid + i * 256;
            const int r = slot >> 3, c8 = (slot & 7) * 8;
            cp16(smem_u32(Kb + r * KS_STRIDE + c8), kp + (size_t)r * NDK + c8);
            cp16(smem_u32(Kb + r * KS_STRIDE + c8 + 4), kp + (size_t)r * NDK + c8 + 4);
            cp16(smem_u32(Vb + r * VS_STRIDE + c8), vp + (size_t)r * NDK + c8);
            cp16(smem_u32(Vb + r * VS_STRIDE + c8 + 4), vp + (size_t)r * NDK + c8 + 4);
        }
        cp_commit();
    }

    for (int jb = 0; jb < njb; ++jb) {
        const int cur = jb & 1;
        float* Ks = smx + cur * KV_BUF;
        float* Vs = Ks + 64 * KS_STRIDE;

        __syncthreads();   // readers of buffer cur^1 (iter jb-1) done
        if (jb + 1 < njb) {
            const int kn = (jb + 1) * 64;
            float* Kb = smx + (cur ^ 1) * KV_BUF;
            float* Vb = Kb + 64 * KS_STRIDE;
#pragma unroll
            for (int i = 0; i < 2; ++i) {
                const int slot = tid + i * 256;
                const int r = slot >> 3, c8 = (slot & 7) * 8;
                cp16(smem_u32(Kb + r * KS_STRIDE + c8), kp + (size_t)(kn + r) * NDK + c8);
                cp16(smem_u32(Kb + r * KS_STRIDE + c8 + 4), kp + (size_t)(kn + r) * NDK + c8 + 4);
                cp16(smem_u32(Vb + r * VS_STRIDE + c8), vp + (size_t)(kn + r) * NDK + c8);
                cp16(smem_u32(Vb + r * VS_STRIDE + c8 + 4), vp + (size_t)(kn + r) * NDK + c8 + 4);
            }
            cp_commit();
            cp_wait<1>();
        } else {
            cp_wait<0>();
        }
        __syncthreads();

        // S = Qtile @ K^T
        float s[8][4] = {};
#pragma unroll
        for (int kk = 0; kk < 8; ++kk) {
            const int kb = kk * 8;
#pragma unroll
            for (int nt = 0; nt < 8; ++nt) {
                unsigned bf[2];
                bf[0] = __float_as_uint(Ks[(nt * 8 + gq) * KS_STRIDE + kb + gr]);
                bf[1] = __float_as_uint(Ks[(nt * 8 + gq) * KS_STRIDE + kb + gr + 4]);
                mma8(s[nt], qf[kk], bf);
            }
        }

        // Causal mask (exact, per element) when this key tile can exceed warp rows
        const int k0 = jb * 64;
        if (k0 + 63 > qb0 + rb) {
            const int qi0 = qb0 + rb + gq;
#pragma unroll
            for (int nt = 0; nt < 8; ++nt) {
                const int kj = k0 + nt * 8 + gr * 2;
                if (kj > qi0) s[nt][0] = -1e30f;
                if (kj + 1 > qi0) s[nt][1] = -1e30f;
                if (kj > qi0 + 8) s[nt][2] = -1e30f;
                if (kj + 1 > qi0 + 8) s[nt][3] = -1e30f;
            }
        }
        // Online softmax
#pragma unroll
        for (int half = 0; half < 2; ++half) {
            float tmax = -1e30f;
#pragma unroll
            for (int nt = 0; nt < 8; ++nt)
                tmax = fmaxf(tmax, fmaxf(s[nt][half * 2], s[nt][half * 2 + 1]));
            tmax = fmaxf(tmax, __shfl_xor_sync(0xffffffffu, tmax, 1));
            tmax = fmaxf(tmax, __shfl_xor_sync(0xffffffffu, tmax, 2));
            const float mnew = fmaxf(mrow[half], tmax);
            const float scl = __expf(mrow[half] - mnew);
            float rsum = 0.0f;
#pragma unroll
            for (int nt = 0; nt < 8; ++nt) {
                const float p0 = __expf(s[nt][half * 2] - mnew);
                const float p1 = __expf(s[nt][half * 2 + 1] - mnew);
                s[nt][half * 2] = p0; s[nt][half * 2 + 1] = p1;
                rsum += p0 + p1;
            }
            rsum += __shfl_xor_sync(0xffffffffu, rsum, 1);
            rsum += __shfl_xor_sync(0xffffffffu, rsum, 2);
            lrow[half] = lrow[half] * scl + rsum;
            mrow[half] = mnew;
#pragma unroll
            for (int nt = 0; nt < 8; ++nt) {
                o[nt][half * 2] *= scl;
                o[nt][half * 2 + 1] *= scl;
            }
        }

        // Stage P (tf32-rounded) into per-warp smem region
#pragma unroll
        for (int nt = 0; nt < 8; ++nt) {
            const int cc = nt * 8 + gr * 2;
            Pw[gq * KS_STRIDE + cc] = f2tf(s[nt][0]);
            Pw[gq * KS_STRIDE + cc + 1] = f2tf(s[nt][1]);
            Pw[(gq + 8) * KS_STRIDE + cc] = f2tf(s[nt][2]);
            Pw[(gq + 8) * KS_STRIDE + cc + 1] = f2tf(s[nt][3]);
        }
        __syncwarp();

        // O += P @ V
#pragma unroll
        for (int kk = 0; kk < 8; ++kk) {
            const int kb = kk * 8;
            unsigned af[4];
            af[0] = __float_as_uint(Pw[gq * KS_STRIDE + kb + gr]);
            af[1] = __float_as_uint(Pw[(gq + 8) * KS_STRIDE + kb + gr]);
            af[2] = __float_as_uint(Pw[gq * KS_STRIDE + kb + gr + 4]);
            af[3] = __float_as_uint(Pw[(gq + 8) * KS_STRIDE + kb + gr + 4]);
#pragma unroll
            for (int nt = 0; nt < 8; ++nt) {
                unsigned bf[2];
                bf[0] = __float_as_uint(Vs[(kb + gr) * VS_STRIDE + nt * 8 + gq]);
                bf[1] = __float_as_uint(Vs[(kb + gr + 4) * VS_STRIDE + nt * 8 + gq]);
                mma8(o[nt], af, bf);
            }
        }
        __syncwarp();
    }

    // Normalize, write ctx tf32-rounded (consumed by out-projection MMA)
    const int b = bh / NH, h = bh % NH;
    const float inv0 = 1.0f / lrow[0], inv1 = 1.0f / lrow[1];
    const int s0 = qb0 + rb + gq;
#pragma unroll
    for (int nt = 0; nt < 8; ++nt) {
        const int dc = h * NDK + nt * 8 + gr * 2;
        float* p0 = g_ctx + ((size_t)b * NS + s0) * ND + dc;
        float* p1 = g_ctx + ((size_t)b * NS + s0 + 8) * ND + dc;
        p0[0] = f2tf(o[nt][0] * inv0); p0[1] = f2tf(o[nt][1] * inv0);
        p1[0] = f2tf(o[nt][2] * inv1); p1[1] = f2tf(o[nt][3] * inv1);
    }
}

// ---------------------------------------------------------------------------
extern "C" void kernel_launch(void* const* d_in, const int* in_sizes, int n_in,
                              void* d_out, int out_size) {
    (void)in_sizes; (void)n_in; (void)out_size;
    const float* Q  = (const float*)d_in[0];
    const float* K  = (const float*)d_in[1];
    const float* V  = (const float*)d_in[2];
    const float* Wq = (const float*)d_in[4];
    const float* Wk = (const float*)d_in[5];
    const float* Wv = (const float*)d_in[6];
    const float* Wo = (const float*)d_in[7];
    float* out = (float*)d_out;

    // Merged Q/K/V projection: one launch, 1152 blocks.
    gemm_mma<0><<<dim3(ND / 64, NM / 128, 3), 128>>>(Q, K, V, Wq, Wk, Wv, nullptr);

    cudaFuncSetAttribute(flash_mma, cudaFuncAttributeMaxDynamicSharedMemorySize, FLASH_SMEM);
    flash_mma<<<dim3(NS / 128, NB * NH), 256, FLASH_SMEM>>>();

    // Output projection: 384 blocks.
    gemm_mma<1><<<dim3(ND / 64, NM / 128, 1), 128>>>(nullptr, nullptr, nullptr,
                                                     Wo, nullptr, nullptr, out);
}

// round 10
// speedup vs baseline: 5.1039x; 1.4270x over previous
#include <cuda_runtime.h>
#include <cuda_fp16.h>
#include <math.h>

#define NB 2
#define NS 2048
#define ND 768
#define NH 12
#define NDK 64
#define NM (NB * NS)

// Internal tensors in fp16 (fp32 accumulate everywhere).
// g_q pre-scaled by 1/8. g_vt is V TRANSPOSED: [b][h][d][s].
__device__ __half g_q[(size_t)NB * NH * NS * NDK];
__device__ __half g_k[(size_t)NB * NH * NS * NDK];
__device__ __half g_vt[(size_t)NB * NH * NDK * NS];
__device__ __half g_ctx[(size_t)NB * NS * ND];

// ---------------------------------------------------------------------------
__device__ __forceinline__ unsigned packh2(float lo, float hi) {
    __half2 h = __floats2half2_rn(lo, hi);
    return *reinterpret_cast<unsigned*>(&h);
}

__device__ __forceinline__ void mma16(float d[4], const unsigned a[4], const unsigned b[2]) {
    asm volatile(
        "mma.sync.aligned.m16n8k16.row.col.f32.f16.f16.f32 "
        "{%0,%1,%2,%3}, {%4,%5,%6,%7}, {%8,%9}, {%0,%1,%2,%3};"
        : "+f"(d[0]), "+f"(d[1]), "+f"(d[2]), "+f"(d[3])
        : "r"(a[0]), "r"(a[1]), "r"(a[2]), "r"(a[3]), "r"(b[0]), "r"(b[1]));
}

__device__ __forceinline__ unsigned smem_u32(const void* p) {
    return (unsigned)__cvta_generic_to_shared(p);
}
__device__ __forceinline__ void cp16(unsigned s, const void* g) {
    asm volatile("cp.async.cg.shared.global [%0], [%1], 16;" :: "r"(s), "l"(g));
}
__device__ __forceinline__ void cp_commit() {
    asm volatile("cp.async.commit_group;" ::: "memory");
}
template <int N>
__device__ __forceinline__ void cp_wait() {
    asm volatile("cp.async.wait_group %0;" :: "n"(N) : "memory");
}

// ---------------------------------------------------------------------------
// GEMM: out = X @ W^T via m16n8k16 fp16 MMA (fp32 accumulate).
// Block tile 128x64, 128 threads (4 warps, 2x2 warp grid, warp tile 64x32).
// cp.async double-buffered k-loop. W (fp32) fragments packed to half2 on load.
// FINAL=0: X fp32 (harness input); grid.z selects Q/K/V; epilogue stores half
//          (Q scaled by 1/8) head-split; V stored TRANSPOSED into g_vt.
// FINAL=1: X = g_ctx (half, raw smem copy); fp32 store into outp.
// ---------------------------------------------------------------------------
#define NKT (ND / 32)   // 24 k-tiles

template <int FINAL>
__global__ __launch_bounds__(128, 4) void gemm_mma(const float* __restrict__ X0,
                                                   const float* __restrict__ X1,
                                                   const float* __restrict__ X2,
                                                   const float* __restrict__ W0,
                                                   const float* __restrict__ W1,
                                                   const float* __restrict__ W2,
                                                   float* __restrict__ outp) {
    // Manual layout: FINAL=0: As fp32 [2][128][36] @0, Bs fp32 [2][64][36] @36864
    //                FINAL=1: Ah half [2][128][40] @0, Bs fp32 [2][64][36] @20480
    __shared__ __align__(16) char smraw[55296];
    float (*As)[128][36] = reinterpret_cast<float (*)[128][36]>(smraw);
    __half (*Ah)[128][40] = reinterpret_cast<__half (*)[128][40]>(smraw);
    float (*Bs)[64][36] = reinterpret_cast<float (*)[64][36]>(smraw + (FINAL ? 20480 : 36864));

    const int z = FINAL ? 0 : blockIdx.z;
    const float* Xf = FINAL ? nullptr : (z == 0 ? X0 : (z == 1 ? X1 : X2));
    const __half* Xh = g_ctx;
    const float* W = FINAL ? W0 : (z == 0 ? W0 : (z == 1 ? W1 : W2));

    const int tid = threadIdx.x;
    const int wid = tid >> 5, lane = tid & 31;
    const int wm = wid >> 1, wn = wid & 1;
    const int gq = lane >> 2, gr = lane & 3;
    const int m0 = blockIdx.y * 128, n0 = blockIdx.x * 64;

    float acc[4][4][4] = {};

    // Prefetch k-tile 0 into buffer 0.
    {
        if (FINAL) {
#pragma unroll
            for (int i = 0; i < 4; ++i) {
                const int slot = tid + i * 128;            // 0..511
                const int row = slot >> 2, c8 = (slot & 3) * 8;
                cp16(smem_u32(&Ah[0][row][c8]), Xh + (size_t)(m0 + row) * ND + c8);
            }
        } else {
#pragma unroll
            for (int i = 0; i < 8; ++i) {
                const int slot = tid + i * 128;            // 0..1023
                const int row = slot >> 3, c = (slot & 7) * 4;
                cp16(smem_u32(&As[0][row][c]), Xf + (size_t)(m0 + row) * ND + c);
            }
        }
#pragma unroll
        for (int i = 0; i < 4; ++i) {
            const int slot = tid + i * 128;                // 0..511
            const int row = slot >> 3, c = (slot & 7) * 4;
            cp16(smem_u32(&Bs[0][row][c]), W + (size_t)(n0 + row) * ND + c);
        }
        cp_commit();
    }

    for (int t = 0; t < NKT; ++t) {
        const int cur = t & 1;
        __syncthreads();
        if (t + 1 < NKT) {
            const int kn = (t + 1) * 32;
            if (FINAL) {
#pragma unroll
                for (int i = 0; i < 4; ++i) {
                    const int slot = tid + i * 128;
                    const int row = slot >> 2, c8 = (slot & 3) * 8;
                    cp16(smem_u32(&Ah[cur ^ 1][row][c8]), Xh + (size_t)(m0 + row) * ND + kn + c8);
                }
            } else {
#pragma unroll
                for (int i = 0; i < 8; ++i) {
                    const int slot = tid + i * 128;
                    const int row = slot >> 3, c = (slot & 7) * 4;
                    cp16(smem_u32(&As[cur ^ 1][row][c]), Xf + (size_t)(m0 + row) * ND + kn + c);
                }
            }
#pragma unroll
            for (int i = 0; i < 4; ++i) {
                const int slot = tid + i * 128;
                const int row = slot >> 3, c = (slot & 7) * 4;
                cp16(smem_u32(&Bs[cur ^ 1][row][c]), W + (size_t)(n0 + row) * ND + kn + c);
            }
            cp_commit();
            cp_wait<1>();
        } else {
            cp_wait<0>();
        }
        __syncthreads();

#pragma unroll
        for (int ks = 0; ks < 2; ++ks) {
            const int kb = ks * 16;
            unsigned af[4][4], bf[4][2];
#pragma unroll
            for (int mt = 0; mt < 4; ++mt) {
                const int rb = wm * 64 + mt * 16;
                if (FINAL) {
                    af[mt][0] = *reinterpret_cast<const unsigned*>(&Ah[cur][rb + gq][kb + 2 * gr]);
                    af[mt][1] = *reinterpret_cast<const unsigned*>(&Ah[cur][rb + 8 + gq][kb + 2 * gr]);
                    af[mt][2] = *reinterpret_cast<const unsigned*>(&Ah[cur][rb + gq][kb + 2 * gr + 8]);
                    af[mt][3] = *reinterpret_cast<const unsigned*>(&Ah[cur][rb + 8 + gq][kb + 2 * gr + 8]);
                } else {
                    float2 a0 = *reinterpret_cast<const float2*>(&As[cur][rb + gq][kb + 2 * gr]);
                    float2 a1 = *reinterpret_cast<const float2*>(&As[cur][rb + 8 + gq][kb + 2 * gr]);
                    float2 a2 = *reinterpret_cast<const float2*>(&As[cur][rb + gq][kb + 2 * gr + 8]);
                    float2 a3 = *reinterpret_cast<const float2*>(&As[cur][rb + 8 + gq][kb + 2 * gr + 8]);
                    af[mt][0] = packh2(a0.x, a0.y);
                    af[mt][1] = packh2(a1.x, a1.y);
                    af[mt][2] = packh2(a2.x, a2.y);
                    af[mt][3] = packh2(a3.x, a3.y);
                }
            }
#pragma unroll
            for (int nt = 0; nt < 4; ++nt) {
                const int nb = wn * 32 + nt * 8;
                float2 b0 = *reinterpret_cast<const float2*>(&Bs[cur][nb + gq][kb + 2 * gr]);
                float2 b1 = *reinterpret_cast<const float2*>(&Bs[cur][nb + gq][kb + 2 * gr + 8]);
                bf[nt][0] = packh2(b0.x, b0.y);
                bf[nt][1] = packh2(b1.x, b1.y);
            }
#pragma unroll
            for (int mt = 0; mt < 4; ++mt)
#pragma unroll
                for (int nt = 0; nt < 4; ++nt) mma16(acc[mt][nt], af[mt], bf[nt]);
        }
    }

    const float escl = (!FINAL && z == 0) ? 0.125f : 1.0f;
#pragma unroll
    for (int mt = 0; mt < 4; ++mt) {
#pragma unroll
        for (int nt = 0; nt < 4; ++nt) {
#pragma unroll
            for (int half = 0; half < 2; ++half) {
                const int m = m0 + wm * 64 + mt * 16 + gq + half * 8;
                const int ncol = n0 + wn * 32 + nt * 8 + gr * 2;
                const float v0 = acc[mt][nt][half * 2 + 0];
                const float v1 = acc[mt][nt][half * 2 + 1];
                if (FINAL) {
                    outp[(size_t)m * ND + ncol] = v0;
                    outp[(size_t)m * ND + ncol + 1] = v1;
                } else {
                    const int b = m >> 11, s = m & (NS - 1);
                    const int h = ncol >> 6, dc = ncol & 63;
                    if (z == 2) {
                        // V: store transposed [b][h][d][s]
                        const size_t base = (((size_t)b * NH + h) * NDK);
                        g_vt[(base + dc) * NS + s] = __float2half_rn(v0);
                        g_vt[(base + dc + 1) * NS + s] = __float2half_rn(v1);
                    } else {
                        __half* dst = (z == 0) ? g_q : g_k;
                        __half2* p = reinterpret_cast<__half2*>(
                            dst + (((size_t)b * NH + h) * NS + s) * NDK + dc);
                        *p = __floats2half2_rn(v0 * escl, v1 * escl);
                    }
                }
            }
        }
    }
}

// ---------------------------------------------------------------------------
// Causal flash attention via m16n8k16 fp16 MMA (fp32 accumulate/softmax).
// BM=128, BN=64, dk=64. 256 threads = 8 warps; warp owns 16 query rows.
// Q fragments in registers from global half. K and V^T tiles double-buffered
// via cp.async. P staged as half2 per warp.
// ---------------------------------------------------------------------------
#define FSTR 72                           // smem row stride in halves
#define KVBUF_H (2 * 64 * FSTR)           // K + Vt per stage, in halves
#define FLASH_SMEM ((2 * KVBUF_H + 8 * 16 * FSTR) * 2)   // 55296 bytes

__global__ __launch_bounds__(256, 2) void flash_mma() {
    extern __shared__ __half smh[];
    __half* Ps = smh + 2 * KVBUF_H;       // 8 x (16 x FSTR)

    const int tid = threadIdx.x;
    const int wid = tid >> 5, lane = tid & 31;
    const int gq = lane >> 2, gr = lane & 3;
    const int qb0 = blockIdx.x * 128;
    const int bh = blockIdx.y;
    const int rb = wid * 16;

    const __half* qp = g_q + (size_t)bh * NS * NDK;
    const __half* kp = g_k + (size_t)bh * NS * NDK;
    const __half* vtp = g_vt + (size_t)bh * NDK * NS;
    __half* Pw = Ps + wid * 16 * FSTR;

    // Q fragments (4 k-steps of 16): one 32-bit load per reg (half2 pairs).
    unsigned qf[4][4];
#pragma unroll
    for (int ks = 0; ks < 4; ++ks) {
        const int kb = ks * 16;
        qf[ks][0] = *reinterpret_cast<const unsigned*>(qp + (size_t)(qb0 + rb + gq) * NDK + kb + 2 * gr);
        qf[ks][1] = *reinterpret_cast<const unsigned*>(qp + (size_t)(qb0 + rb + 8 + gq) * NDK + kb + 2 * gr);
        qf[ks][2] = *reinterpret_cast<const unsigned*>(qp + (size_t)(qb0 + rb + gq) * NDK + kb + 2 * gr + 8);
        qf[ks][3] = *reinterpret_cast<const unsigned*>(qp + (size_t)(qb0 + rb + 8 + gq) * NDK + kb + 2 * gr + 8);
    }

    float o[8][4] = {};
    float mrow[2] = {-1e30f, -1e30f};
    float lrow[2] = {0.0f, 0.0f};

    const int njb = 2 * blockIdx.x + 2;

    // Prefetch tile 0 into stage 0. K: 512 chunks, Vt: 512 chunks; 256 threads.
    {
        __half* Kb = smh;
        __half* Vb = smh + 64 * FSTR;
#pragma unroll
        for (int i = 0; i < 2; ++i) {
            const int slot = tid + i * 256;
            const int r = slot >> 3, c8 = (slot & 7) * 8;
            cp16(smem_u32(Kb + r * FSTR + c8), kp + (size_t)r * NDK + c8);
            cp16(smem_u32(Vb + r * FSTR + c8), vtp + (size_t)r * NS + c8);
        }
        cp_commit();
    }

    for (int jb = 0; jb < njb; ++jb) {
        const int cur = jb & 1;
        __half* Ks = smh + cur * KVBUF_H;
        __half* Vs = Ks + 64 * FSTR;

        __syncthreads();
        if (jb + 1 < njb) {
            const int kn = (jb + 1) * 64;
            __half* Kb = smh + (cur ^ 1) * KVBUF_H;
            __half* Vb = Kb + 64 * FSTR;
#pragma unroll
            for (int i = 0; i < 2; ++i) {
                const int slot = tid + i * 256;
                const int r = slot >> 3, c8 = (slot & 7) * 8;
                cp16(smem_u32(Kb + r * FSTR + c8), kp + (size_t)(kn + r) * NDK + c8);
                cp16(smem_u32(Vb + r * FSTR + c8), vtp + (size_t)r * NS + kn + c8);
            }
            cp_commit();
            cp_wait<1>();
        } else {
            cp_wait<0>();
        }
        __syncthreads();

        // S = Qtile @ K^T
        float s[8][4] = {};
#pragma unroll
        for (int ks = 0; ks < 4; ++ks) {
            const int kb = ks * 16;
#pragma unroll
            for (int nt = 0; nt < 8; ++nt) {
                unsigned bf[2];
                bf[0] = *reinterpret_cast<const unsigned*>(&Ks[(nt * 8 + gq) * FSTR + kb + 2 * gr]);
                bf[1] = *reinterpret_cast<const unsigned*>(&Ks[(nt * 8 + gq) * FSTR + kb + 2 * gr + 8]);
                mma16(s[nt], qf[ks], bf);
            }
        }

        // Causal mask when this key tile can exceed warp rows
        const int k0 = jb * 64;
        if (k0 + 63 > qb0 + rb) {
            const int qi0 = qb0 + rb + gq;
#pragma unroll
            for (int nt = 0; nt < 8; ++nt) {
                const int kj = k0 + nt * 8 + gr * 2;
                if (kj > qi0) s[nt][0] = -1e30f;
                if (kj + 1 > qi0) s[nt][1] = -1e30f;
                if (kj > qi0 + 8) s[nt][2] = -1e30f;
                if (kj + 1 > qi0 + 8) s[nt][3] = -1e30f;
            }
        }
        // Online softmax (fp32)
#pragma unroll
        for (int half = 0; half < 2; ++half) {
            float tmax = -1e30f;
#pragma unroll
            for (int nt = 0; nt < 8; ++nt)
                tmax = fmaxf(tmax, fmaxf(s[nt][half * 2], s[nt][half * 2 + 1]));
            tmax = fmaxf(tmax, __shfl_xor_sync(0xffffffffu, tmax, 1));
            tmax = fmaxf(tmax, __shfl_xor_sync(0xffffffffu, tmax, 2));
            const float mnew = fmaxf(mrow[half], tmax);
            const float scl = __expf(mrow[half] - mnew);
            float rsum = 0.0f;
#pragma unroll
            for (int nt = 0; nt < 8; ++nt) {
                const float p0 = __expf(s[nt][half * 2] - mnew);
                const float p1 = __expf(s[nt][half * 2 + 1] - mnew);
                s[nt][half * 2] = p0; s[nt][half * 2 + 1] = p1;
                rsum += p0 + p1;
            }
            rsum += __shfl_xor_sync(0xffffffffu, rsum, 1);
            rsum += __shfl_xor_sync(0xffffffffu, rsum, 2);
            lrow[half] = lrow[half] * scl + rsum;
            mrow[half] = mnew;
#pragma unroll
            for (int nt = 0; nt < 8; ++nt) {
                o[nt][half * 2] *= scl;
                o[nt][half * 2 + 1] *= scl;
            }
        }

        // Stage P as half2 into per-warp smem region
#pragma unroll
        for (int nt = 0; nt < 8; ++nt) {
            const int cc = nt * 8 + 2 * gr;
            *reinterpret_cast<__half2*>(&Pw[gq * FSTR + cc]) =
                __floats2half2_rn(s[nt][0], s[nt][1]);
            *reinterpret_cast<__half2*>(&Pw[(gq + 8) * FSTR + cc]) =
                __floats2half2_rn(s[nt][2], s[nt][3]);
        }
        __syncwarp();

        // O += P @ V   (B-fragments from transposed V tile: adjacent k pairs)
#pragma unroll
        for (int ks = 0; ks < 4; ++ks) {
            const int kb = ks * 16;
            unsigned af[4];
            af[0] = *reinterpret_cast<const unsigned*>(&Pw[gq * FSTR + kb + 2 * gr]);
            af[1] = *reinterpret_cast<const unsigned*>(&Pw[(gq + 8) * FSTR + kb + 2 * gr]);
            af[2] = *reinterpret_cast<const unsigned*>(&Pw[gq * FSTR + kb + 2 * gr + 8]);
            af[3] = *reinterpret_cast<const unsigned*>(&Pw[(gq + 8) * FSTR + kb + 2 * gr + 8]);
#pragma unroll
            for (int nt = 0; nt < 8; ++nt) {
                unsigned bf[2];
                bf[0] = *reinterpret_cast<const unsigned*>(&Vs[(nt * 8 + gq) * FSTR + kb + 2 * gr]);
                bf[1] = *reinterpret_cast<const unsigned*>(&Vs[(nt * 8 + gq) * FSTR + kb + 2 * gr + 8]);
                mma16(o[nt], af, bf);
            }
        }
        __syncwarp();
    }

    // Normalize (fp32), write ctx as half2
    const int b = bh / NH, h = bh % NH;
    const float inv0 = 1.0f / lrow[0], inv1 = 1.0f / lrow[1];
    const int s0 = qb0 + rb + gq;
#pragma unroll
    for (int nt = 0; nt < 8; ++nt) {
        const int dc = h * NDK + nt * 8 + 2 * gr;
        *reinterpret_cast<__half2*>(&g_ctx[((size_t)b * NS + s0) * ND + dc]) =
            __floats2half2_rn(o[nt][0] * inv0, o[nt][1] * inv0);
        *reinterpret_cast<__half2*>(&g_ctx[((size_t)b * NS + s0 + 8) * ND + dc]) =
            __floats2half2_rn(o[nt][2] * inv1, o[nt][3] * inv1);
    }
}

// ---------------------------------------------------------------------------
extern "C" void kernel_launch(void* const* d_in, const int* in_sizes, int n_in,
                              void* d_out, int out_size) {
    (void)in_sizes; (void)n_in; (void)out_size;
    const float* Q  = (const float*)d_in[0];
    const float* K  = (const float*)d_in[1];
    const float* V  = (const float*)d_in[2];
    const float* Wq = (const float*)d_in[4];
    const float* Wk = (const float*)d_in[5];
    const float* Wv = (const float*)d_in[6];
    const float* Wo = (const float*)d_in[7];
    float* out = (float*)d_out;

    // Merged Q/K/V projection: one launch, 1152 blocks.
    gemm_mma<0><<<dim3(ND / 64, NM / 128, 3), 128>>>(Q, K, V, Wq, Wk, Wv, nullptr);

    cudaFuncSetAttribute(flash_mma, cudaFuncAttributeMaxDynamicSharedMemorySize, FLASH_SMEM);
    flash_mma<<<dim3(NS / 128, NB * NH), 256, FLASH_SMEM>>>();

    // Output projection: 384 blocks.
    gemm_mma<1><<<dim3(ND / 64, NM / 128, 1), 128>>>(nullptr, nullptr, nullptr,
                                                     Wo, nullptr, nullptr, out);
}

// round 13
// speedup vs baseline: 6.5574x; 1.2848x over previous
#include <cuda_runtime.h>
#include <cuda_fp16.h>
#include <math.h>

#define NB 2
#define NS 2048
#define ND 768
#define NH 12
#define NDK 64
#define NM (NB * NS)
#define XN (NM * ND)
#define WN (ND * ND)

// Half-precision copies of inputs (one-time conversion pass).
__device__ __half g_xh[3][XN];     // Q, K, V inputs
__device__ __half g_wh[4][WN];     // Wq, Wk, Wv, Wo
// Internal tensors (fp16, fp32 accumulate everywhere).
// g_q pre-scaled by 1/8. g_vt is V TRANSPOSED: [b][h][d][s].
__device__ __half g_q[(size_t)NB * NH * NS * NDK];
__device__ __half g_k[(size_t)NB * NH * NS * NDK];
__device__ __half g_vt[(size_t)NB * NH * NDK * NS];
__device__ __half g_ctx[(size_t)NB * NS * ND];

// ---------------------------------------------------------------------------
__device__ __forceinline__ void mma16(float d[4], const unsigned a[4], const unsigned b[2]) {
    asm volatile(
        "mma.sync.aligned.m16n8k16.row.col.f32.f16.f16.f32 "
        "{%0,%1,%2,%3}, {%4,%5,%6,%7}, {%8,%9}, {%0,%1,%2,%3};"
        : "+f"(d[0]), "+f"(d[1]), "+f"(d[2]), "+f"(d[3])
        : "r"(a[0]), "r"(a[1]), "r"(a[2]), "r"(a[3]), "r"(b[0]), "r"(b[1]));
}

__device__ __forceinline__ void ldm4(unsigned r[4], unsigned addr) {
    asm volatile("ldmatrix.sync.aligned.m8n8.x4.shared.b16 {%0,%1,%2,%3}, [%4];"
                 : "=r"(r[0]), "=r"(r[1]), "=r"(r[2]), "=r"(r[3]) : "r"(addr));
}

__device__ __forceinline__ unsigned smem_u32(const void* p) {
    return (unsigned)__cvta_generic_to_shared(p);
}
__device__ __forceinline__ void cp16(unsigned s, const void* g) {
    asm volatile("cp.async.cg.shared.global [%0], [%1], 16;" :: "r"(s), "l"(g));
}
__device__ __forceinline__ void cp_commit() {
    asm volatile("cp.async.commit_group;" ::: "memory");
}
template <int N>
__device__ __forceinline__ void cp_wait() {
    asm volatile("cp.async.wait_group %0;" :: "n"(N) : "memory");
}

// ---------------------------------------------------------------------------
// Conversion pass: fp32 inputs -> fp16 device globals (rn rounding).
// grid.y selects segment: 0..2 = X(Q,K,V), 3..6 = W(q,k,v,o).
// ---------------------------------------------------------------------------
__global__ __launch_bounds__(256) void convert_f2h(const float* __restrict__ X0,
                                                   const float* __restrict__ X1,
                                                   const float* __restrict__ X2,
                                                   const float* __restrict__ W0,
                                                   const float* __restrict__ W1,
                                                   const float* __restrict__ W2,
                                                   const float* __restrict__ W3) {
    const int seg = blockIdx.y;
    const float* src = (seg == 0) ? X0 : (seg == 1) ? X1 : (seg == 2) ? X2
                     : (seg == 3) ? W0 : (seg == 4) ? W1 : (seg == 5) ? W2 : W3;
    __half* dst = (seg < 3) ? g_xh[seg] : g_wh[seg - 3];
    const int n4 = ((seg < 3) ? XN : WN) / 4;
    for (int i = blockIdx.x * blockDim.x + threadIdx.x; i < n4;
         i += gridDim.x * blockDim.x) {
        float4 v = reinterpret_cast<const float4*>(src)[i];
        __half2 h0 = __floats2half2_rn(v.x, v.y);
        __half2 h1 = __floats2half2_rn(v.z, v.w);
        uint2 u;
        u.x = *reinterpret_cast<unsigned*>(&h0);
        u.y = *reinterpret_cast<unsigned*>(&h1);
        reinterpret_cast<uint2*>(dst)[i] = u;
    }
}

// ---------------------------------------------------------------------------
// GEMM: out = X @ W^T, all-fp16 smem, ldmatrix fragments, fp32 accumulate.
// Block tile 128x128, 256 threads (8 warps, 2x4), warp tile 64x32, k-tile 64.
// cp.async double-buffered. Dynamic smem: 2 stages x (A 128x72 + B 128x72).
// FINAL=0: grid.z selects Q/K/V; stores half head-split (Q *0.125, V transposed).
// FINAL=1: X = g_ctx, W = Wo(half); fp32 store into outp.
// ---------------------------------------------------------------------------
#define GSTR 72                 // smem row stride in halves
#define ATS (128 * GSTR)        // one A stage, in halves
#define GEMM_SMEM (4 * ATS * 2) // bytes: 2 stages A + 2 stages B = 73728
#define NKT (ND / 64)           // 12 k-tiles

template <int FINAL>
__global__ __launch_bounds__(256) void gemm_h(float* __restrict__ outp) {
    extern __shared__ __half sm[];       // A stages @0, B stages @2*ATS

    const int z = FINAL ? 3 : blockIdx.z;
    const __half* X = FINAL ? g_ctx : g_xh[blockIdx.z];
    const __half* W = g_wh[z];

    const int tid = threadIdx.x;
    const int wid = tid >> 5, lane = tid & 31;
    const int wm = wid >> 2, wn = wid & 3;       // 2 x 4 warp grid
    const int gq = lane >> 2, gr = lane & 3;
    const int m0 = blockIdx.y * 128, n0 = blockIdx.x * 128;

    // ldmatrix per-lane address components
    const int a_r = (lane & 7) + ((lane >> 3) & 1) * 8;   // row within 16
    const int a_c = (lane >> 4) * 8;                      // 0 or 8
    const int b_r = (lane & 7) + ((lane >> 4) & 1) * 8;   // row within 16
    const int b_c = ((lane >> 3) & 1) * 8;                // 0 or 8

    float acc[4][4][4] = {};

    // Stage fill: A rows 128 x 64 halves (8 chunks/row), same for B. 4 iters.
    {
#pragma unroll
        for (int i = 0; i < 4; ++i) {
            const int slot = tid + i * 256;                 // 0..1023
            const int row = slot >> 3, c = (slot & 7) * 8;  // halves
            cp16(smem_u32(&sm[row * GSTR + c]), X + (size_t)(m0 + row) * ND + c);
            cp16(smem_u32(&sm[2 * ATS + row * GSTR + c]), W + (size_t)(n0 + row) * ND + c);
        }
        cp_commit();
    }

    for (int t = 0; t < NKT; ++t) {
        const int cur = t & 1;
        __syncthreads();
        if (t + 1 < NKT) {
            const int kn = (t + 1) * 64;
            const int nb = cur ^ 1;
#pragma unroll
            for (int i = 0; i < 4; ++i) {
                const int slot = tid + i * 256;
                const int row = slot >> 3, c = (slot & 7) * 8;
                cp16(smem_u32(&sm[nb * ATS + row * GSTR + c]),
                     X + (size_t)(m0 + row) * ND + kn + c);
                cp16(smem_u32(&sm[(2 + nb) * ATS + row * GSTR + c]),
                     W + (size_t)(n0 + row) * ND + kn + c);
            }
            cp_commit();
            cp_wait<1>();
        } else {
            cp_wait<0>();
        }
        __syncthreads();

        const __half* Ac = sm + cur * ATS;
        const __half* Bc = sm + (2 + cur) * ATS;
#pragma unroll
        for (int ks = 0; ks < 4; ++ks) {
            const int kb = ks * 16;
            unsigned af[4][4], bf[2][4];
#pragma unroll
            for (int mt = 0; mt < 4; ++mt) {
                const int rb = wm * 64 + mt * 16;
                ldm4(af[mt], smem_u32(Ac + (rb + a_r) * GSTR + kb + a_c));
            }
#pragma unroll
            for (int p = 0; p < 2; ++p) {
                const int nbr = wn * 32 + p * 16;
                ldm4(bf[p], smem_u32(Bc + (nbr + b_r) * GSTR + kb + b_c));
            }
#pragma unroll
            for (int mt = 0; mt < 4; ++mt) {
#pragma unroll
                for (int p = 0; p < 2; ++p) {
                    mma16(acc[mt][2 * p + 0], af[mt], &bf[p][0]);
                    mma16(acc[mt][2 * p + 1], af[mt], &bf[p][2]);
                }
            }
        }
    }

    const float escl = (!FINAL && z == 0) ? 0.125f : 1.0f;
#pragma unroll
    for (int mt = 0; mt < 4; ++mt) {
#pragma unroll
        for (int nt = 0; nt < 4; ++nt) {
#pragma unroll
            for (int half = 0; half < 2; ++half) {
                const int m = m0 + wm * 64 + mt * 16 + gq + half * 8;
                const int ncol = n0 + wn * 32 + nt * 8 + gr * 2;
                const float v0 = acc[mt][nt][half * 2 + 0];
                const float v1 = acc[mt][nt][half * 2 + 1];
                if (FINAL) {
                    outp[(size_t)m * ND + ncol] = v0;
                    outp[(size_t)m * ND + ncol + 1] = v1;
                } else {
                    const int b = m >> 11, s = m & (NS - 1);
                    const int h = ncol >> 6, dc = ncol & 63;
                    if (z == 2) {
                        const size_t base = ((size_t)b * NH + h) * NDK;
                        g_vt[(base + dc) * NS + s] = __float2half_rn(v0);
                        g_vt[(base + dc + 1) * NS + s] = __float2half_rn(v1);
                    } else {
                        __half* dst = (z == 0) ? g_q : g_k;
                        __half2* p = reinterpret_cast<__half2*>(
                            dst + (((size_t)b * NH + h) * NS + s) * NDK + dc);
                        *p = __floats2half2_rn(v0 * escl, v1 * escl);
                    }
                }
            }
        }
    }
}

// ---------------------------------------------------------------------------
// Causal flash attention via m16n8k16 fp16 MMA (fp32 accumulate/softmax).
// BM=128, BN=64, dk=64. 256 threads = 8 warps; warp owns 16 query rows.
// (unchanged from R10 -- known good; next optimization target)
// ---------------------------------------------------------------------------
#define FSTR 72
#define KVBUF_H (2 * 64 * FSTR)
#define FLASH_SMEM ((2 * KVBUF_H + 8 * 16 * FSTR) * 2)

__global__ __launch_bounds__(256, 2) void flash_mma() {
    extern __shared__ __half smh[];
    __half* Ps = smh + 2 * KVBUF_H;

    const int tid = threadIdx.x;
    const int wid = tid >> 5, lane = tid & 31;
    const int gq = lane >> 2, gr = lane & 3;
    const int qb0 = blockIdx.x * 128;
    const int bh = blockIdx.y;
    const int rb = wid * 16;

    const __half* qp = g_q + (size_t)bh * NS * NDK;
    const __half* kp = g_k + (size_t)bh * NS * NDK;
    const __half* vtp = g_vt + (size_t)bh * NDK * NS;
    __half* Pw = Ps + wid * 16 * FSTR;

    unsigned qf[4][4];
#pragma unroll
    for (int ks = 0; ks < 4; ++ks) {
        const int kb = ks * 16;
        qf[ks][0] = *reinterpret_cast<const unsigned*>(qp + (size_t)(qb0 + rb + gq) * NDK + kb + 2 * gr);
        qf[ks][1] = *reinterpret_cast<const unsigned*>(qp + (size_t)(qb0 + rb + 8 + gq) * NDK + kb + 2 * gr);
        qf[ks][2] = *reinterpret_cast<const unsigned*>(qp + (size_t)(qb0 + rb + gq) * NDK + kb + 2 * gr + 8);
        qf[ks][3] = *reinterpret_cast<const unsigned*>(qp + (size_t)(qb0 + rb + 8 + gq) * NDK + kb + 2 * gr + 8);
    }

    float o[8][4] = {};
    float mrow[2] = {-1e30f, -1e30f};
    float lrow[2] = {0.0f, 0.0f};

    const int njb = 2 * blockIdx.x + 2;

    {
        __half* Kb = smh;
        __half* Vb = smh + 64 * FSTR;
#pragma unroll
        for (int i = 0; i < 2; ++i) {
            const int slot = tid + i * 256;
            const int r = slot >> 3, c8 = (slot & 7) * 8;
            cp16(smem_u32(Kb + r * FSTR + c8), kp + (size_t)r * NDK + c8);
            cp16(smem_u32(Vb + r * FSTR + c8), vtp + (size_t)r * NS + c8);
        }
        cp_commit();
    }

    for (int jb = 0; jb < njb; ++jb) {
        const int cur = jb & 1;
        __half* Ks = smh + cur * KVBUF_H;
        __half* Vs = Ks + 64 * FSTR;

        __syncthreads();
        if (jb + 1 < njb) {
            const int kn = (jb + 1) * 64;
            __half* Kb = smh + (cur ^ 1) * KVBUF_H;
            __half* Vb = Kb + 64 * FSTR;
#pragma unroll
            for (int i = 0; i < 2; ++i) {
                const int slot = tid + i * 256;
                const int r = slot >> 3, c8 = (slot & 7) * 8;
                cp16(smem_u32(Kb + r * FSTR + c8), kp + (size_t)(kn + r) * NDK + c8);
                cp16(smem_u32(Vb + r * FSTR + c8), vtp + (size_t)r * NS + kn + c8);
            }
            cp_commit();
            cp_wait<1>();
        } else {
            cp_wait<0>();
        }
        __syncthreads();

        float s[8][4] = {};
#pragma unroll
        for (int ks = 0; ks < 4; ++ks) {
            const int kb = ks * 16;
#pragma unroll
            for (int nt = 0; nt < 8; ++nt) {
                unsigned bf[2];
                bf[0] = *reinterpret_cast<const unsigned*>(&Ks[(nt * 8 + gq) * FSTR + kb + 2 * gr]);
                bf[1] = *reinterpret_cast<const unsigned*>(&Ks[(nt * 8 + gq) * FSTR + kb + 2 * gr + 8]);
                mma16(s[nt], qf[ks], bf);
            }
        }

        const int k0 = jb * 64;
        if (k0 + 63 > qb0 + rb) {
            const int qi0 = qb0 + rb + gq;
#pragma unroll
            for (int nt = 0; nt < 8; ++nt) {
                const int kj = k0 + nt * 8 + gr * 2;
                if (kj > qi0) s[nt][0] = -1e30f;
                if (kj + 1 > qi0) s[nt][1] = -1e30f;
                if (kj > qi0 + 8) s[nt][2] = -1e30f;
                if (kj + 1 > qi0 + 8) s[nt][3] = -1e30f;
            }
        }
#pragma unroll
        for (int half = 0; half < 2; ++half) {
            float tmax = -1e30f;
#pragma unroll
            for (int nt = 0; nt < 8; ++nt)
                tmax = fmaxf(tmax, fmaxf(s[nt][half * 2], s[nt][half * 2 + 1]));
            tmax = fmaxf(tmax, __shfl_xor_sync(0xffffffffu, tmax, 1));
            tmax = fmaxf(tmax, __shfl_xor_sync(0xffffffffu, tmax, 2));
            const float mnew = fmaxf(mrow[half], tmax);
            const float scl = __expf(mrow[half] - mnew);
            float rsum = 0.0f;
#pragma unroll
            for (int nt = 0; nt < 8; ++nt) {
                const float p0 = __expf(s[nt][half * 2] - mnew);
                const float p1 = __expf(s[nt][half * 2 + 1] - mnew);
                s[nt][half * 2] = p0; s[nt][half * 2 + 1] = p1;
                rsum += p0 + p1;
            }
            rsum += __shfl_xor_sync(0xffffffffu, rsum, 1);
            rsum += __shfl_xor_sync(0xffffffffu, rsum, 2);
            lrow[half] = lrow[half] * scl + rsum;
            mrow[half] = mnew;
#pragma unroll
            for (int nt = 0; nt < 8; ++nt) {
                o[nt][half * 2] *= scl;
                o[nt][half * 2 + 1] *= scl;
            }
        }

#pragma unroll
        for (int nt = 0; nt < 8; ++nt) {
            const int cc = nt * 8 + 2 * gr;
            *reinterpret_cast<__half2*>(&Pw[gq * FSTR + cc]) =
                __floats2half2_rn(s[nt][0], s[nt][1]);
            *reinterpret_cast<__half2*>(&Pw[(gq + 8) * FSTR + cc]) =
                __floats2half2_rn(s[nt][2], s[nt][3]);
        }
        __syncwarp();

#pragma unroll
        for (int ks = 0; ks < 4; ++ks) {
            const int kb = ks * 16;
            unsigned af[4];
            af[0] = *reinterpret_cast<const unsigned*>(&Pw[gq * FSTR + kb + 2 * gr]);
            af[1] = *reinterpret_cast<const unsigned*>(&Pw[(gq + 8) * FSTR + kb + 2 * gr]);
            af[2] = *reinterpret_cast<const unsigned*>(&Pw[gq * FSTR + kb + 2 * gr + 8]);
            af[3] = *reinterpret_cast<const unsigned*>(&Pw[(gq + 8) * FSTR + kb + 2 * gr + 8]);
#pragma unroll
            for (int nt = 0; nt < 8; ++nt) {
                unsigned bf[2];
                bf[0] = *reinterpret_cast<const unsigned*>(&Vs[(nt * 8 + gq) * FSTR + kb + 2 * gr]);
                bf[1] = *reinterpret_cast<const unsigned*>(&Vs[(nt * 8 + gq) * FSTR + kb + 2 * gr + 8]);
                mma16(o[nt], af, bf);
            }
        }
        __syncwarp();
    }

    const int b = bh / NH, h = bh % NH;
    const float inv0 = 1.0f / lrow[0], inv1 = 1.0f / lrow[1];
    const int s0 = qb0 + rb + gq;
#pragma unroll
    for (int nt = 0; nt < 8; ++nt) {
        const int dc = h * NDK + nt * 8 + 2 * gr;
        *reinterpret_cast<__half2*>(&g_ctx[((size_t)b * NS + s0) * ND + dc]) =
            __floats2half2_rn(o[nt][0] * inv0, o[nt][1] * inv0);
        *reinterpret_cast<__half2*>(&g_ctx[((size_t)b * NS + s0 + 8) * ND + dc]) =
            __floats2half2_rn(o[nt][2] * inv1, o[nt][3] * inv1);
    }
}

// ---------------------------------------------------------------------------
extern "C" void kernel_launch(void* const* d_in, const int* in_sizes, int n_in,
                              void* d_out, int out_size) {
    (void)in_sizes; (void)n_in; (void)out_size;
    const float* Q  = (const float*)d_in[0];
    const float* K  = (const float*)d_in[1];
    const float* V  = (const float*)d_in[2];
    const float* Wq = (const float*)d_in[4];
    const float* Wk = (const float*)d_in[5];
    const float* Wv = (const float*)d_in[6];
    const float* Wo = (const float*)d_in[7];
    float* out = (float*)d_out;

    cudaFuncSetAttribute(gemm_h<0>, cudaFuncAttributeMaxDynamicSharedMemorySize, GEMM_SMEM);
    cudaFuncSetAttribute(gemm_h<1>, cudaFuncAttributeMaxDynamicSharedMemorySize, GEMM_SMEM);
    cudaFuncSetAttribute(flash_mma, cudaFuncAttributeMaxDynamicSharedMemorySize, FLASH_SMEM);

    // 1) fp32 -> fp16 conversion of X and W.
    convert_f2h<<<dim3(512, 7), 256>>>(Q, K, V, Wq, Wk, Wv, Wo);

    // 2) Merged Q/K/V projection (576 blocks).
    gemm_h<0><<<dim3(ND / 128, NM / 128, 3), 256, GEMM_SMEM>>>(nullptr);

    // 3) Flash attention.
    flash_mma<<<dim3(NS / 128, NB * NH), 256, FLASH_SMEM>>>();

    // 4) Output projection (192 blocks).
    gemm_h<1><<<dim3(ND / 128, NM / 128, 1), 256, GEMM_SMEM>>>(out);
}

// round 15
// speedup vs baseline: 7.3308x; 1.1179x over previous
#include <cuda_runtime.h>
#include <cuda_fp16.h>
#include <math.h>

#define NB 2
#define NS 2048
#define ND 768
#define NH 12
#define NDK 64
#define NM (NB * NS)
#define XN (NM * ND)
#define WN (ND * ND)

// Half-precision copies of inputs (one-time conversion pass).
__device__ __half g_xh[3][XN];     // Q, K, V inputs
__device__ __half g_wh[4][WN];     // Wq, Wk, Wv, Wo
// Internal tensors (fp16, fp32 accumulate everywhere).
// g_q pre-scaled by 1/8. g_vt is V TRANSPOSED: [b][h][d][s].
__device__ __half g_q[(size_t)NB * NH * NS * NDK];
__device__ __half g_k[(size_t)NB * NH * NS * NDK];
__device__ __half g_vt[(size_t)NB * NH * NDK * NS];
__device__ __half g_ctx[(size_t)NB * NS * ND];

// ---------------------------------------------------------------------------
__device__ __forceinline__ unsigned packh2(float lo, float hi) {
    __half2 h = __floats2half2_rn(lo, hi);
    return *reinterpret_cast<unsigned*>(&h);
}

__device__ __forceinline__ void mma16(float d[4], const unsigned a[4], const unsigned b[2]) {
    asm volatile(
        "mma.sync.aligned.m16n8k16.row.col.f32.f16.f16.f32 "
        "{%0,%1,%2,%3}, {%4,%5,%6,%7}, {%8,%9}, {%0,%1,%2,%3};"
        : "+f"(d[0]), "+f"(d[1]), "+f"(d[2]), "+f"(d[3])
        : "r"(a[0]), "r"(a[1]), "r"(a[2]), "r"(a[3]), "r"(b[0]), "r"(b[1]));
}

__device__ __forceinline__ void ldm4(unsigned r[4], unsigned addr) {
    asm volatile("ldmatrix.sync.aligned.m8n8.x4.shared.b16 {%0,%1,%2,%3}, [%4];"
                 : "=r"(r[0]), "=r"(r[1]), "=r"(r[2]), "=r"(r[3]) : "r"(addr));
}

__device__ __forceinline__ unsigned smem_u32(const void* p) {
    return (unsigned)__cvta_generic_to_shared(p);
}
__device__ __forceinline__ void cp16(unsigned s, const void* g) {
    asm volatile("cp.async.cg.shared.global [%0], [%1], 16;" :: "r"(s), "l"(g));
}
__device__ __forceinline__ void cp_commit() {
    asm volatile("cp.async.commit_group;" ::: "memory");
}
template <int N>
__device__ __forceinline__ void cp_wait() {
    asm volatile("cp.async.wait_group %0;" :: "n"(N) : "memory");
}

// ---------------------------------------------------------------------------
// Conversion pass: fp32 inputs -> fp16 device globals (rn rounding).
// ---------------------------------------------------------------------------
__global__ __launch_bounds__(256) void convert_f2h(const float* __restrict__ X0,
                                                   const float* __restrict__ X1,
                                                   const float* __restrict__ X2,
                                                   const float* __restrict__ W0,
                                                   const float* __restrict__ W1,
                                                   const float* __restrict__ W2,
                                                   const float* __restrict__ W3) {
    const int seg = blockIdx.y;
    const float* src = (seg == 0) ? X0 : (seg == 1) ? X1 : (seg == 2) ? X2
                     : (seg == 3) ? W0 : (seg == 4) ? W1 : (seg == 5) ? W2 : W3;
    __half* dst = (seg < 3) ? g_xh[seg] : g_wh[seg - 3];
    const int n4 = ((seg < 3) ? XN : WN) / 4;
    for (int i = blockIdx.x * blockDim.x + threadIdx.x; i < n4;
         i += gridDim.x * blockDim.x) {
        float4 v = reinterpret_cast<const float4*>(src)[i];
        __half2 h0 = __floats2half2_rn(v.x, v.y);
        __half2 h1 = __floats2half2_rn(v.z, v.w);
        uint2 u;
        u.x = *reinterpret_cast<unsigned*>(&h0);
        u.y = *reinterpret_cast<unsigned*>(&h1);
        reinterpret_cast<uint2*>(dst)[i] = u;
    }
}

// ---------------------------------------------------------------------------
// QKV GEMM: g_{q,k,vt} = X @ W^T, fp16 smem + ldmatrix, fp32 accumulate.
// Block tile 128x128, 256 threads (8 warps, 2x4), warp tile 64x32, k-tile 64.
// grid.z selects Q/K/V; stores half head-split (Q *0.125, V transposed).
// ---------------------------------------------------------------------------
#define GSTR 72                 // smem row stride in halves
#define ATS (128 * GSTR)        // one 128-row stage, in halves
#define GEMM_SMEM (4 * ATS * 2) // 73728 bytes
#define NKT (ND / 64)           // 12 k-tiles

__global__ __launch_bounds__(256) void gemm_qkv() {
    extern __shared__ __half sm[];       // A stages @0, B stages @2*ATS

    const int z = blockIdx.z;
    const __half* X = g_xh[z];
    const __half* W = g_wh[z];

    const int tid = threadIdx.x;
    const int wid = tid >> 5, lane = tid & 31;
    const int wm = wid >> 2, wn = wid & 3;       // 2 x 4 warp grid
    const int gq = lane >> 2, gr = lane & 3;
    const int m0 = blockIdx.y * 128, n0 = blockIdx.x * 128;

    const int a_r = (lane & 7) + ((lane >> 3) & 1) * 8;
    const int a_c = (lane >> 4) * 8;
    const int b_r = (lane & 7) + ((lane >> 4) & 1) * 8;
    const int b_c = ((lane >> 3) & 1) * 8;

    float acc[4][4][4] = {};

    {
#pragma unroll
        for (int i = 0; i < 4; ++i) {
            const int slot = tid + i * 256;
            const int row = slot >> 3, c = (slot & 7) * 8;
            cp16(smem_u32(&sm[row * GSTR + c]), X + (size_t)(m0 + row) * ND + c);
            cp16(smem_u32(&sm[2 * ATS + row * GSTR + c]), W + (size_t)(n0 + row) * ND + c);
        }
        cp_commit();
    }

    for (int t = 0; t < NKT; ++t) {
        const int cur = t & 1;
        __syncthreads();
        if (t + 1 < NKT) {
            const int kn = (t + 1) * 64;
            const int nb = cur ^ 1;
#pragma unroll
            for (int i = 0; i < 4; ++i) {
                const int slot = tid + i * 256;
                const int row = slot >> 3, c = (slot & 7) * 8;
                cp16(smem_u32(&sm[nb * ATS + row * GSTR + c]),
                     X + (size_t)(m0 + row) * ND + kn + c);
                cp16(smem_u32(&sm[(2 + nb) * ATS + row * GSTR + c]),
                     W + (size_t)(n0 + row) * ND + kn + c);
            }
            cp_commit();
            cp_wait<1>();
        } else {
            cp_wait<0>();
        }
        __syncthreads();

        const __half* Ac = sm + cur * ATS;
        const __half* Bc = sm + (2 + cur) * ATS;
#pragma unroll
        for (int ks = 0; ks < 4; ++ks) {
            const int kb = ks * 16;
            unsigned af[4][4], bf[2][4];
#pragma unroll
            for (int mt = 0; mt < 4; ++mt) {
                const int rb = wm * 64 + mt * 16;
                ldm4(af[mt], smem_u32(Ac + (rb + a_r) * GSTR + kb + a_c));
            }
#pragma unroll
            for (int p = 0; p < 2; ++p) {
                const int nbr = wn * 32 + p * 16;
                ldm4(bf[p], smem_u32(Bc + (nbr + b_r) * GSTR + kb + b_c));
            }
#pragma unroll
            for (int mt = 0; mt < 4; ++mt) {
#pragma unroll
                for (int p = 0; p < 2; ++p) {
                    mma16(acc[mt][2 * p + 0], af[mt], &bf[p][0]);
                    mma16(acc[mt][2 * p + 1], af[mt], &bf[p][2]);
                }
            }
        }
    }

    const float escl = (z == 0) ? 0.125f : 1.0f;
#pragma unroll
    for (int mt = 0; mt < 4; ++mt) {
#pragma unroll
        for (int nt = 0; nt < 4; ++nt) {
#pragma unroll
            for (int half = 0; half < 2; ++half) {
                const int m = m0 + wm * 64 + mt * 16 + gq + half * 8;
                const int ncol = n0 + wn * 32 + nt * 8 + gr * 2;
                const float v0 = acc[mt][nt][half * 2 + 0];
                const float v1 = acc[mt][nt][half * 2 + 1];
                const int b = m >> 11, s = m & (NS - 1);
                const int h = ncol >> 6, dc = ncol & 63;
                if (z == 2) {
                    const size_t base = ((size_t)b * NH + h) * NDK;
                    g_vt[(base + dc) * NS + s] = __float2half_rn(v0);
                    g_vt[(base + dc + 1) * NS + s] = __float2half_rn(v1);
                } else {
                    __half* dst = (z == 0) ? g_q : g_k;
                    __half2* p = reinterpret_cast<__half2*>(
                        dst + (((size_t)b * NH + h) * NS + s) * NDK + dc);
                    *p = __floats2half2_rn(v0 * escl, v1 * escl);
                }
            }
        }
    }
}

// ---------------------------------------------------------------------------
// Output GEMM: out = ctx @ Wo^T, block tile 128x64 (384 blocks for occupancy).
// 256 threads (8 warps, 4m x 2n), warp tile 32x32, k-tile 64, double-buffered.
// ---------------------------------------------------------------------------
#define BTS (64 * GSTR)
#define OGEMM_SMEM ((2 * ATS + 2 * BTS) * 2)   // 55296 bytes

__global__ __launch_bounds__(256) void gemm_out(float* __restrict__ outp) {
    extern __shared__ __half sm[];       // A stages @0, B stages @2*ATS

    const __half* X = g_ctx;
    const __half* W = g_wh[3];

    const int tid = threadIdx.x;
    const int wid = tid >> 5, lane = tid & 31;
    const int wm = wid >> 1, wn = wid & 1;       // 4 x 2 warp grid
    const int gq = lane >> 2, gr = lane & 3;
    const int m0 = blockIdx.y * 128, n0 = blockIdx.x * 64;

    const int a_r = (lane & 7) + ((lane >> 3) & 1) * 8;
    const int a_c = (lane >> 4) * 8;
    const int b_r = (lane & 7) + ((lane >> 4) & 1) * 8;
    const int b_c = ((lane >> 3) & 1) * 8;

    float acc[2][4][4] = {};

    {
#pragma unroll
        for (int i = 0; i < 4; ++i) {
            const int slot = tid + i * 256;                 // 0..1023
            const int row = slot >> 3, c = (slot & 7) * 8;
            cp16(smem_u32(&sm[row * GSTR + c]), X + (size_t)(m0 + row) * ND + c);
        }
#pragma unroll
        for (int i = 0; i < 2; ++i) {
            const int slot = tid + i * 256;                 // 0..511
            const int row = slot >> 3, c = (slot & 7) * 8;
            cp16(smem_u32(&sm[2 * ATS + row * GSTR + c]), W + (size_t)(n0 + row) * ND + c);
        }
        cp_commit();
    }

    for (int t = 0; t < NKT; ++t) {
        const int cur = t & 1;
        __syncthreads();
        if (t + 1 < NKT) {
            const int kn = (t + 1) * 64;
            const int nb = cur ^ 1;
#pragma unroll
            for (int i = 0; i < 4; ++i) {
                const int slot = tid + i * 256;
                const int row = slot >> 3, c = (slot & 7) * 8;
                cp16(smem_u32(&sm[nb * ATS + row * GSTR + c]),
                     X + (size_t)(m0 + row) * ND + kn + c);
            }
#pragma unroll
            for (int i = 0; i < 2; ++i) {
                const int slot = tid + i * 256;
                const int row = slot >> 3, c = (slot & 7) * 8;
                cp16(smem_u32(&sm[2 * ATS + nb * BTS + row * GSTR + c]),
                     W + (size_t)(n0 + row) * ND + kn + c);
            }
            cp_commit();
            cp_wait<1>();
        } else {
            cp_wait<0>();
        }
        __syncthreads();

        const __half* Ac = sm + cur * ATS;
        const __half* Bc = sm + 2 * ATS + cur * BTS;
#pragma unroll
        for (int ks = 0; ks < 4; ++ks) {
            const int kb = ks * 16;
            unsigned af[2][4], bf[2][4];
#pragma unroll
            for (int mt = 0; mt < 2; ++mt) {
                const int rb = wm * 32 + mt * 16;
                ldm4(af[mt], smem_u32(Ac + (rb + a_r) * GSTR + kb + a_c));
            }
#pragma unroll
            for (int p = 0; p < 2; ++p) {
                const int nbr = wn * 32 + p * 16;
                ldm4(bf[p], smem_u32(Bc + (nbr + b_r) * GSTR + kb + b_c));
            }
#pragma unroll
            for (int mt = 0; mt < 2; ++mt) {
#pragma unroll
                for (int p = 0; p < 2; ++p) {
                    mma16(acc[mt][2 * p + 0], af[mt], &bf[p][0]);
                    mma16(acc[mt][2 * p + 1], af[mt], &bf[p][2]);
                }
            }
        }
    }

#pragma unroll
    for (int mt = 0; mt < 2; ++mt) {
#pragma unroll
        for (int nt = 0; nt < 4; ++nt) {
#pragma unroll
            for (int half = 0; half < 2; ++half) {
                const int m = m0 + wm * 32 + mt * 16 + gq + half * 8;
                const int ncol = n0 + wn * 32 + nt * 8 + gr * 2;
                outp[(size_t)m * ND + ncol] = acc[mt][nt][half * 2 + 0];
                outp[(size_t)m * ND + ncol + 1] = acc[mt][nt][half * 2 + 1];
            }
        }
    }
}

// ---------------------------------------------------------------------------
// Causal flash attention: fp16 MMA, fp32 softmax/accum.
// BM=128, BN=64, dk=64. 256 threads = 8 warps; warp owns 16 query rows.
// P kept in REGISTERS (QK D-fragment == PV A-fragment layout; zero staging).
// K / V^T fragments via ldmatrix.x4. K/V double-buffered cp.async.
// ---------------------------------------------------------------------------
#define FSTR 72
#define KVBUF_H (2 * 64 * FSTR)
#define FLASH_SMEM (2 * KVBUF_H * 2)     // 36864 bytes

__global__ __launch_bounds__(256, 2) void flash_mma() {
    extern __shared__ __half smh[];

    const int tid = threadIdx.x;
    const int wid = tid >> 5, lane = tid & 31;
    const int gq = lane >> 2, gr = lane & 3;
    const int qb0 = blockIdx.x * 128;
    const int bh = blockIdx.y;
    const int rb = wid * 16;

    const int b_r = (lane & 7) + ((lane >> 4) & 1) * 8;
    const int b_c = ((lane >> 3) & 1) * 8;

    const __half* qp = g_q + (size_t)bh * NS * NDK;
    const __half* kp = g_k + (size_t)bh * NS * NDK;
    const __half* vtp = g_vt + (size_t)bh * NDK * NS;

    // Q fragments from global (pre-rounded, pre-scaled).
    unsigned qf[4][4];
#pragma unroll
    for (int ks = 0; ks < 4; ++ks) {
        const int kb = ks * 16;
        qf[ks][0] = *reinterpret_cast<const unsigned*>(qp + (size_t)(qb0 + rb + gq) * NDK + kb + 2 * gr);
        qf[ks][1] = *reinterpret_cast<const unsigned*>(qp + (size_t)(qb0 + rb + 8 + gq) * NDK + kb + 2 * gr);
        qf[ks][2] = *reinterpret_cast<const unsigned*>(qp + (size_t)(qb0 + rb + gq) * NDK + kb + 2 * gr + 8);
        qf[ks][3] = *reinterpret_cast<const unsigned*>(qp + (size_t)(qb0 + rb + 8 + gq) * NDK + kb + 2 * gr + 8);
    }

    float o[8][4] = {};
    float mrow[2] = {-1e30f, -1e30f};
    float lrow[2] = {0.0f, 0.0f};

    const int njb = 2 * blockIdx.x + 2;

    {
        __half* Kb = smh;
        __half* Vb = smh + 64 * FSTR;
#pragma unroll
        for (int i = 0; i < 2; ++i) {
            const int slot = tid + i * 256;
            const int r = slot >> 3, c8 = (slot & 7) * 8;
            cp16(smem_u32(Kb + r * FSTR + c8), kp + (size_t)r * NDK + c8);
            cp16(smem_u32(Vb + r * FSTR + c8), vtp + (size_t)r * NS + c8);
        }
        cp_commit();
    }

    for (int jb = 0; jb < njb; ++jb) {
        const int cur = jb & 1;
        __half* Ks = smh + cur * KVBUF_H;
        __half* Vs = Ks + 64 * FSTR;

        __syncthreads();
        if (jb + 1 < njb) {
            const int kn = (jb + 1) * 64;
            __half* Kb = smh + (cur ^ 1) * KVBUF_H;
            __half* Vb = Kb + 64 * FSTR;
#pragma unroll
            for (int i = 0; i < 2; ++i) {
                const int slot = tid + i * 256;
                const int r = slot >> 3, c8 = (slot & 7) * 8;
                cp16(smem_u32(Kb + r * FSTR + c8), kp + (size_t)(kn + r) * NDK + c8);
                cp16(smem_u32(Vb + r * FSTR + c8), vtp + (size_t)r * NS + kn + c8);
            }
            cp_commit();
            cp_wait<1>();
        } else {
            cp_wait<0>();
        }
        __syncthreads();

        // S = Qtile @ K^T  (ldmatrix B-fragments, 16 keys per nt2)
        float s[8][4] = {};
#pragma unroll
        for (int ks = 0; ks < 4; ++ks) {
            const int kb = ks * 16;
#pragma unroll
            for (int nt2 = 0; nt2 < 4; ++nt2) {
                unsigned bf[4];
                ldm4(bf, smem_u32(Ks + (nt2 * 16 + b_r) * FSTR + kb + b_c));
                mma16(s[2 * nt2 + 0], qf[ks], &bf[0]);
                mma16(s[2 * nt2 + 1], qf[ks], &bf[2]);
            }
        }

        // Causal mask
        const int k0 = jb * 64;
        if (k0 + 63 > qb0 + rb) {
            const int qi0 = qb0 + rb + gq;
#pragma unroll
            for (int nt = 0; nt < 8; ++nt) {
                const int kj = k0 + nt * 8 + gr * 2;
                if (kj > qi0) s[nt][0] = -1e30f;
                if (kj + 1 > qi0) s[nt][1] = -1e30f;
                if (kj > qi0 + 8) s[nt][2] = -1e30f;
                if (kj + 1 > qi0 + 8) s[nt][3] = -1e30f;
            }
        }
        // Online softmax (fp32)
#pragma unroll
        for (int half = 0; half < 2; ++half) {
            float tmax = -1e30f;
#pragma unroll
            for (int nt = 0; nt < 8; ++nt)
                tmax = fmaxf(tmax, fmaxf(s[nt][half * 2], s[nt][half * 2 + 1]));
            tmax = fmaxf(tmax, __shfl_xor_sync(0xffffffffu, tmax, 1));
            tmax = fmaxf(tmax, __shfl_xor_sync(0xffffffffu, tmax, 2));
            const float mnew = fmaxf(mrow[half], tmax);
            const float scl = __expf(mrow[half] - mnew);
            float rsum = 0.0f;
#pragma unroll
            for (int nt = 0; nt < 8; ++nt) {
                const float p0 = __expf(s[nt][half * 2] - mnew);
                const float p1 = __expf(s[nt][half * 2 + 1] - mnew);
                s[nt][half * 2] = p0; s[nt][half * 2 + 1] = p1;
                rsum += p0 + p1;
            }
            rsum += __shfl_xor_sync(0xffffffffu, rsum, 1);
            rsum += __shfl_xor_sync(0xffffffffu, rsum, 2);
            lrow[half] = lrow[half] * scl + rsum;
            mrow[half] = mnew;
#pragma unroll
            for (int nt = 0; nt < 8; ++nt) {
                o[nt][half * 2] *= scl;
                o[nt][half * 2 + 1] *= scl;
            }
        }

        // O += P @ V : P stays in registers.
        // QK D-fragment (row gq / gq+8, cols 2gr,2gr+1 of 8-col group nt)
        // == PV A-fragment for 16-key block ks (groups 2ks, 2ks+1).
#pragma unroll
        for (int ks = 0; ks < 4; ++ks) {
            const int kb = ks * 16;
            unsigned af[4];
            af[0] = packh2(s[2 * ks][0], s[2 * ks][1]);
            af[1] = packh2(s[2 * ks][2], s[2 * ks][3]);
            af[2] = packh2(s[2 * ks + 1][0], s[2 * ks + 1][1]);
            af[3] = packh2(s[2 * ks + 1][2], s[2 * ks + 1][3]);
#pragma unroll
            for (int nt2 = 0; nt2 < 4; ++nt2) {
                unsigned bf[4];
                ldm4(bf, smem_u32(Vs + (nt2 * 16 + b_r) * FSTR + kb + b_c));
                mma16(o[2 * nt2 + 0], af, &bf[0]);
                mma16(o[2 * nt2 + 1], af, &bf[2]);
            }
        }
    }

    // Normalize (fp32), write ctx as half2
    const int b = bh / NH, h = bh % NH;
    const float inv0 = 1.0f / lrow[0], inv1 = 1.0f / lrow[1];
    const int s0 = qb0 + rb + gq;
#pragma unroll
    for (int nt = 0; nt < 8; ++nt) {
        const int dc = h * NDK + nt * 8 + 2 * gr;
        *reinterpret_cast<__half2*>(&g_ctx[((size_t)b * NS + s0) * ND + dc]) =
            __floats2half2_rn(o[nt][0] * inv0, o[nt][1] * inv0);
        *reinterpret_cast<__half2*>(&g_ctx[((size_t)b * NS + s0 + 8) * ND + dc]) =
            __floats2half2_rn(o[nt][2] * inv1, o[nt][3] * inv1);
    }
}

// ---------------------------------------------------------------------------
extern "C" void kernel_launch(void* const* d_in, const int* in_sizes, int n_in,
                              void* d_out, int out_size) {
    (void)in_sizes; (void)n_in; (void)out_size;
    const float* Q  = (const float*)d_in[0];
    const float* K  = (const float*)d_in[1];
    const float* V  = (const float*)d_in[2];
    const float* Wq = (const float*)d_in[4];
    const float* Wk = (const float*)d_in[5];
    const float* Wv = (const float*)d_in[6];
    const float* Wo = (const float*)d_in[7];
    float* out = (float*)d_out;

    cudaFuncSetAttribute(gemm_qkv, cudaFuncAttributeMaxDynamicSharedMemorySize, GEMM_SMEM);
    cudaFuncSetAttribute(gemm_out, cudaFuncAttributeMaxDynamicSharedMemorySize, OGEMM_SMEM);
    cudaFuncSetAttribute(flash_mma, cudaFuncAttributeMaxDynamicSharedMemorySize, FLASH_SMEM);

    // 1) fp32 -> fp16 conversion of X and W.
    convert_f2h<<<dim3(512, 7), 256>>>(Q, K, V, Wq, Wk, Wv, Wo);

    // 2) Merged Q/K/V projection (576 blocks).
    gemm_qkv<<<dim3(ND / 128, NM / 128, 3), 256, GEMM_SMEM>>>();

    // 3) Flash attention (register-P, ldmatrix).
    flash_mma<<<dim3(NS / 128, NB * NH), 256, FLASH_SMEM>>>();

    // 4) Output projection (384 blocks).
    gemm_out<<<dim3(ND / 64, NM / 128), 256, OGEMM_SMEM>>>(out);
}